// round 4
// baseline (speedup 1.0000x reference)
#include <cuda_runtime.h>
#include <cstdint>
#include <cstddef>

// ============================================================================
// Arch feature detection: tcgen05 needs the 'a' target (sm_103a).
// The harness also builds a base compute_103 PTX pass -> guarded fallback.
// ============================================================================
#if defined(__CUDA_ARCH_FEAT_SM103_ALL) || defined(__CUDA_ARCH_FEAT_SM100_ALL) || defined(__CUDA_ARCH_FEAT_SM101_ALL)
#define HAS_TCGEN05 1
#else
#define HAS_TCGEN05 0
#endif

// ============================================================================
// Problem constants
// ============================================================================
#define M_DIM 4096
#define K_DIM 4096
#define N_DIM 11008
#define NW_TOT (N_DIM / 8)
#define GROUP 128

#define TILE_K 32                     // 32 tf32 = 128B = one SW128 row
#define K_CHUNKS (K_DIM / TILE_K)     // 128
#define M_TILES 32                    // 128-row A tiles
#define N_TILES 43                    // 256-row W tiles
#define PAIR_M 16                     // 256-row pair tiles (cg2)

#define A_BLK_BYTES (128 * TILE_K * 4)    // 16384 (one CTA's A half)
#define B_BLK_BYTES (256 * TILE_K * 4)    // 32768 (full 256-row W block in scratch)
#define B_HALF_BYTES (128 * TILE_K * 4)   // 16384 (one CTA's B half)

#define STAGES 6
#define STAGE_BYTES (A_BLK_BYTES + B_HALF_BYTES)      // 32768
#define GEMM_SMEM_BYTES (1024 + STAGES * STAGE_BYTES) // 197632

// fallback pipeline (base compute_103 pass only)
#define FB_STAGES 4
#define FB_STAGE_BYTES (A_BLK_BYTES + B_BLK_BYTES)    // 49152 (4*49152+1024 = 197632)

// idesc kind::tf32: dfmt=F32(1)<<4, a=TF32(2)<<7, b=TF32(2)<<10, N/8@[17:23), M/16@[24:29)
#define MMA_IDESC_TF32_CG2 ((1u << 4) | (2u << 7) | (2u << 10) | (32u << 17) | (16u << 24))

// Scratch: pre-tiled, pre-SW128-swizzled tf32 operands.
__device__ __align__(1024) float g_As[(size_t)M_TILES * K_CHUNKS * (128 * TILE_K)];
__device__ __align__(1024) float g_Ws[(size_t)N_TILES * K_CHUNKS * (256 * TILE_K)];

// ============================================================================
// Base-ISA helpers
// ============================================================================
__device__ __forceinline__ uint32_t smem_u32(const void* p) {
    uint32_t a;
    asm("{ .reg .u64 t; cvta.to.shared.u64 t, %1; cvt.u32.u64 %0, t; }" : "=r"(a) : "l"(p));
    return a;
}

__device__ __forceinline__ uint32_t sw128(uint32_t byte_off) {
    return byte_off ^ ((byte_off >> 3) & 0x70);
}

__device__ __forceinline__ uint32_t f2tf32(float v) {
    uint32_t r;
    asm("cvt.rna.tf32.f32 %0, %1;" : "=r"(r) : "f"(v));
    return r;
}

#define MBAR_INIT(addr, cnt) \
    asm volatile("mbarrier.init.shared.b64 [%0], %1;" :: "r"(addr), "r"((uint32_t)(cnt)) : "memory")

#define MBAR_EXPECT_TX(addr, bytes) \
    asm volatile("mbarrier.arrive.expect_tx.shared.b64 _, [%0], %1;" :: "r"(addr), "r"((uint32_t)(bytes)) : "memory")

#define MBAR_ARRIVE(addr) \
    asm volatile("mbarrier.arrive.release.cta.shared.b64 _, [%0];" :: "r"(addr) : "memory")

// cluster-release arrive on leader CTA (rank 0) barrier at the same offset
#define MBAR_ARRIVE_LEADER(addr) \
    asm volatile("{ .reg .b32 ra; mapa.shared::cluster.u32 ra, %0, 0; " \
                 "mbarrier.arrive.release.cluster.shared::cluster.b64 _, [ra]; }" \
                 :: "r"(addr) : "memory")

#define CLUSTER_SYNC() do { \
    asm volatile("barrier.cluster.arrive.aligned;" ::: "memory"); \
    asm volatile("barrier.cluster.wait.aligned;" ::: "memory"); \
} while (0)

__device__ __forceinline__ void mbar_wait(uint32_t mbar, uint32_t parity) {
    uint32_t done;
    asm volatile(
        "{ .reg .pred p; mbarrier.try_wait.parity.acquire.cta.shared::cta.b64 p, [%1], %2; selp.b32 %0, 1, 0, p; }"
        : "=r"(done) : "r"(mbar), "r"(parity) : "memory");
    if (!done) {
        asm volatile(
            "{ .reg .pred P1;\n"
            "WL_%=: mbarrier.try_wait.parity.acquire.cta.shared::cta.b64 P1, [%0], %1, 0x989680;\n"
            "@P1 bra.uni WD_%=;\n"
            "bra.uni WL_%=;\n"
            "WD_%=: }"
            :: "r"(mbar), "r"(parity) : "memory");
    }
}

// cluster-scope acquire wait (for barriers armed by remote arrives / cg2 commits)
__device__ __forceinline__ void mbar_wait_cl(uint32_t mbar, uint32_t parity) {
    uint32_t done;
    asm volatile(
        "{ .reg .pred p; mbarrier.try_wait.parity.acquire.cluster.shared::cta.b64 p, [%1], %2; selp.b32 %0, 1, 0, p; }"
        : "=r"(done) : "r"(mbar), "r"(parity) : "memory");
    if (!done) {
        asm volatile(
            "{ .reg .pred P1;\n"
            "WL_%=: mbarrier.try_wait.parity.acquire.cluster.shared::cta.b64 P1, [%0], %1, 0x989680;\n"
            "@P1 bra.uni WD_%=;\n"
            "bra.uni WL_%=;\n"
            "WD_%=: }"
            :: "r"(mbar), "r"(parity) : "memory");
    }
}

__device__ __forceinline__ void bulk_g2s(uint32_t dst_smem, const void* src_gmem,
                                         uint32_t bytes, uint32_t mbar) {
    asm volatile(
        "cp.async.bulk.shared::cluster.global.mbarrier::complete_tx::bytes [%0], [%1], %2, [%3];"
        :: "r"(dst_smem), "l"(src_gmem), "r"(bytes), "r"(mbar) : "memory");
}

__device__ __forceinline__ uint32_t cluster_rank() {
    uint32_t r;
    asm("mov.u32 %0, %%cluster_ctarank;" : "=r"(r));
    return r;
}

// legacy tf32 mma (sm_80 base ISA) -- fallback path only
__device__ __forceinline__ void mma_sync_tf32(float* d, const uint32_t* a, const uint32_t* b) {
    asm volatile(
        "mma.sync.aligned.m16n8k8.row.col.f32.tf32.tf32.f32 "
        "{%0, %1, %2, %3}, {%4, %5, %6, %7}, {%8, %9}, {%0, %1, %2, %3};"
        : "+f"(d[0]), "+f"(d[1]), "+f"(d[2]), "+f"(d[3])
        : "r"(a[0]), "r"(a[1]), "r"(a[2]), "r"(a[3]), "r"(b[0]), "r"(b[1]));
}

#if HAS_TCGEN05
// ============================================================================
// sm_103a-only helpers
// ============================================================================
__device__ __forceinline__ uint32_t elect_one() {
    uint32_t p;
    asm volatile("{ .reg .pred p; elect.sync _|p, 0xFFFFFFFF; selp.b32 %0, 1, 0, p; }" : "=r"(p));
    return p;
}

__device__ __forceinline__ uint64_t make_desc_sw128(uint32_t addr) {
    const uint64_t base = (uint64_t(2) << 61) | (uint64_t(1) << 46) |
                          (uint64_t(64) << 32) | (uint64_t(1) << 16);
    return base | ((uint64_t)(addr >> 4) & 0x3FFF);
}

__device__ __forceinline__ void mma_tf32_ss_cg2(uint32_t d_tmem, uint64_t a_desc, uint64_t b_desc,
                                                uint32_t idesc, bool acc) {
    uint32_t en = acc ? 1u : 0u;
    asm volatile(
        "{\n\t"
        ".reg .pred p;\n\t"
        "setp.ne.u32 p, %5, 0;\n\t"
        "tcgen05.mma.cta_group::2.kind::tf32 [%0], %1, %2, %3, "
        "{%4, %4, %4, %4, %4, %4, %4, %4}, p;\n\t"
        "}"
        :: "r"(d_tmem), "l"(a_desc), "l"(b_desc), "r"(idesc), "r"(0u), "r"(en) : "memory");
}

#define TCGEN05_COMMIT_MC_CG2(mbar, mask) \
    asm volatile("tcgen05.commit.cta_group::2.mbarrier::arrive::one.shared::cluster.multicast::cluster.b64 [%0], %1;" \
                 :: "r"(mbar), "h"((uint16_t)(mask)) : "memory")

__device__ __forceinline__ void tcgen05_ld_x32(uint32_t* r, uint32_t tmem_addr) {
    asm volatile(
        "tcgen05.ld.sync.aligned.32x32b.x32.b32 "
        "{%0, %1, %2, %3, %4, %5, %6, %7, "
        " %8, %9, %10, %11, %12, %13, %14, %15, "
        " %16, %17, %18, %19, %20, %21, %22, %23, "
        " %24, %25, %26, %27, %28, %29, %30, %31}, [%32];"
        : "=r"(r[0]), "=r"(r[1]), "=r"(r[2]), "=r"(r[3]),
          "=r"(r[4]), "=r"(r[5]), "=r"(r[6]), "=r"(r[7]),
          "=r"(r[8]), "=r"(r[9]), "=r"(r[10]), "=r"(r[11]),
          "=r"(r[12]), "=r"(r[13]), "=r"(r[14]), "=r"(r[15]),
          "=r"(r[16]), "=r"(r[17]), "=r"(r[18]), "=r"(r[19]),
          "=r"(r[20]), "=r"(r[21]), "=r"(r[22]), "=r"(r[23]),
          "=r"(r[24]), "=r"(r[25]), "=r"(r[26]), "=r"(r[27]),
          "=r"(r[28]), "=r"(r[29]), "=r"(r[30]), "=r"(r[31])
        : "r"(tmem_addr));
}
#endif  // HAS_TCGEN05

// ============================================================================
// Kernel 1: dequantize int4 -> tf32, [N,K] pre-tiled + SW128-swizzled.
// SMEM-free value path (SW128 permutes 16B units; aligned uint4 STG lands right).
// ============================================================================
__global__ void __launch_bounds__(256) dequant_kernel(
    const int* __restrict__ qweight,
    const float* __restrict__ scales,
    const int* __restrict__ qzeros
) {
    const int bid = blockIdx.x;
    const int n_tile = bid >> 7;
    const int k_chunk = bid & 127;
    const int k0 = k_chunk * TILE_K;
    const int g = k0 >> 7;
    const int t = threadIdx.x;

    __shared__ uint32_t sq[TILE_K * 33];
    __shared__ uint32_t sz[32];

    {
        const int k = t >> 3;
        const int nw0 = (t & 7) * 4;
        const uint32_t* src = (const uint32_t*)qweight +
                              (size_t)(k0 + k) * NW_TOT + n_tile * 32 + nw0;
        #pragma unroll
        for (int i = 0; i < 4; i++) sq[k * 33 + nw0 + i] = src[i];
        if (t < 32) sz[t] = ((const uint32_t*)qzeros)[(size_t)g * NW_TOT + n_tile * 32 + t];
    }
    __syncthreads();

    char* dst_base = (char*)(g_Ws + (size_t)bid * (256 * TILE_K));
    #pragma unroll
    for (int p = 0; p < 8; p++) {
        const int idx = p * 256 + t;
        const int n_local = idx >> 3;
        const int u = idx & 7;
        const int nw = n_local >> 3;
        const int nib = (n_local & 7) * 4;
        const float z = (float)((sz[nw] >> nib) & 15u);
        const float s = __ldg(scales + (size_t)g * N_DIM + n_tile * 256 + n_local);
        uint32_t w[4];
        #pragma unroll
        for (int e = 0; e < 4; e++) {
            const float q = (float)((sq[(u * 4 + e) * 33 + nw] >> nib) & 15u);
            w[e] = f2tf32((q - z) * s);
        }
        *(uint4*)(dst_base + sw128((uint32_t)(n_local * 128 + u * 16))) =
            make_uint4(w[0], w[1], w[2], w[3]);
    }
}

// ============================================================================
// Kernel 2: activations fp32 -> tf32(RNA), SMEM-free, pre-tiled + swizzled
// ============================================================================
__global__ void __launch_bounds__(256) aconv_kernel(const float* __restrict__ inp) {
    const int bid = blockIdx.x;
    const int m_tile = bid >> 7;
    const int k_chunk = bid & 127;
    const size_t base_in = (size_t)(m_tile * 128) * K_DIM + k_chunk * TILE_K;
    char* dst_base = (char*)(g_As + (size_t)bid * (128 * TILE_K));
    const int t = threadIdx.x;

    #pragma unroll
    for (int p = 0; p < 4; p++) {
        const int idx = p * 256 + t;
        const int m_local = idx >> 3;
        const int u = idx & 7;
        const float4 f = *(const float4*)(inp + base_in + (size_t)m_local * K_DIM + u * 4);
        uint4 w = make_uint4(f2tf32(f.x), f2tf32(f.y), f2tf32(f.z), f2tf32(f.w));
        *(uint4*)(dst_base + sw128((uint32_t)(m_local * 128 + u * 16))) = w;
    }
}

// ============================================================================
// Kernel 3: cg2 GEMM. Cluster of 2 CTAs computes a 256M x 256N tile.
// Each CTA loads its 128 M-rows of A and 128 N-rows of B (cg2 B split).
// 6-stage bulk-copy pipeline, tcgen05.mma.cta_group::2.kind::tf32,
// fused bias + SiLU + mul epilogue. grid = 1376 (cluster 2), block = 256.
// ============================================================================
__global__ void __launch_bounds__(256, 1) gemm_kernel(
    const float* __restrict__ bias,
    const float* __restrict__ mul,
    float* __restrict__ out
) {
    extern __shared__ char smem[];
    const uint32_t smem_base = smem_u32(smem);
    const uint32_t data_base = (smem_base + 128 + 1023) & ~1023u;

    const int tid = threadIdx.x;
    const int wid = tid >> 5;
    const int lid = tid & 31;
    const int bid = blockIdx.x;
    const int pair = bid >> 1;
    const int pm = pair & (PAIR_M - 1);   // m-fast: concurrent pairs share B via L2
    const int n_tile = pair >> 4;

    const uint32_t LFULL0 = smem_base + 8;     // 6 x 8B, local fill (tx)
    const uint32_t PFULL0 = smem_base + 56;    // 6 x 8B, leader-only, count=2
    const uint32_t EMPTY0 = smem_base + 104;   // 6 x 8B, count=1 (mc commit)
    const uint32_t DONE   = smem_base + 152;

#if HAS_TCGEN05
    const uint32_t rank = cluster_rank();

    if (wid == 0) {
        asm volatile("tcgen05.alloc.cta_group::2.sync.aligned.shared::cta.b32 [%0], %1;"
                     :: "r"(smem_base), "r"(256u) : "memory");
    }
    if (tid == 0) {
        #pragma unroll
        for (int s = 0; s < STAGES; s++) {
            MBAR_INIT(LFULL0 + s * 8, 1);
            MBAR_INIT(PFULL0 + s * 8, 2);
            MBAR_INIT(EMPTY0 + s * 8, 1);
        }
        MBAR_INIT(DONE, 1);
        asm volatile("fence.proxy.async.shared::cta;" ::: "memory");
    }
    __syncthreads();
    CLUSTER_SYNC();   // peer barriers live before remote arrives / peer-SMEM mma reads

    uint32_t tmem_base;
    asm volatile("ld.shared.b32 %0, [%1];" : "=r"(tmem_base) : "r"(smem_base));

    const char* a_src = reinterpret_cast<const char*>(g_As) +
                        (size_t)(pm * 2 + rank) * K_CHUNKS * A_BLK_BYTES;
    const char* b_src = reinterpret_cast<const char*>(g_Ws) +
                        (size_t)n_tile * K_CHUNKS * B_BLK_BYTES + rank * B_HALF_BYTES;

    if (wid == 0) {
        // producer: fill stages, EMPTY-gated refill
        if (elect_one()) {
            #pragma unroll
            for (int j = 0; j < STAGES; j++) {
                const uint32_t fb = LFULL0 + j * 8;
                MBAR_EXPECT_TX(fb, STAGE_BYTES);
                bulk_g2s(data_base + j * STAGE_BYTES, a_src + (size_t)j * A_BLK_BYTES,
                         A_BLK_BYTES, fb);
                bulk_g2s(data_base + j * STAGE_BYTES + A_BLK_BYTES,
                         b_src + (size_t)j * B_BLK_BYTES, B_HALF_BYTES, fb);
            }
            #pragma unroll 1
            for (int j = STAGES; j < K_CHUNKS; j++) {
                const int s = j % STAGES;
                mbar_wait_cl(EMPTY0 + s * 8, ((j - STAGES) / STAGES) & 1);
                const uint32_t fb = LFULL0 + s * 8;
                MBAR_EXPECT_TX(fb, STAGE_BYTES);
                bulk_g2s(data_base + s * STAGE_BYTES, a_src + (size_t)j * A_BLK_BYTES,
                         A_BLK_BYTES, fb);
                bulk_g2s(data_base + s * STAGE_BYTES + A_BLK_BYTES,
                         b_src + (size_t)j * B_BLK_BYTES, B_HALF_BYTES, fb);
            }
        }
        __syncwarp();
    } else if (wid == 1) {
        // forwarder: local fill complete -> arrive on leader's PFULL[s]
        if (elect_one()) {
            #pragma unroll 1
            for (int j = 0; j < K_CHUNKS; j++) {
                const int s = j % STAGES;
                mbar_wait(LFULL0 + s * 8, (j / STAGES) & 1);
                MBAR_ARRIVE_LEADER(PFULL0 + s * 8);
            }
        }
        __syncwarp();
    } else if (wid == 2 && rank == 0) {
        // mma driver (leader only)
        if (elect_one()) {
            #pragma unroll 1
            for (int j = 0; j < K_CHUNKS; j++) {
                const int s = j % STAGES;
                mbar_wait_cl(PFULL0 + s * 8, (j / STAGES) & 1);
                const uint64_t a_desc = make_desc_sw128(data_base + s * STAGE_BYTES);
                const uint64_t b_desc = make_desc_sw128(data_base + s * STAGE_BYTES + A_BLK_BYTES);
                #pragma unroll
                for (int ks = 0; ks < 4; ks++)
                    mma_tf32_ss_cg2(tmem_base, a_desc + ks * 2, b_desc + ks * 2,
                                    MMA_IDESC_TF32_CG2, (j | ks) != 0);
                TCGEN05_COMMIT_MC_CG2(EMPTY0 + s * 8, 0x3);
            }
            TCGEN05_COMMIT_MC_CG2(DONE, 0x3);
        }
        __syncwarp();
    }

    // ---------------- epilogue: 8 warps, each CTA reads its own 128 rows ----------
    mbar_wait_cl(DONE, 0);
    asm volatile("tcgen05.fence::after_thread_sync;" ::: "memory");

    const int m = pm * 256 + rank * 128 + (wid & 3) * 32 + lid;
    const int half = wid >> 2;
    const int n_base = n_tile * 256 + half * 128;
    const float4* mul4 = reinterpret_cast<const float4*>(mul + (size_t)m * N_DIM + n_base);
    float4* out4 = reinterpret_cast<float4*>(out + (size_t)m * N_DIM + n_base);

    #pragma unroll 1
    for (int cc = 0; cc < 4; cc++) {
        uint32_t d[32];
        tcgen05_ld_x32(d, tmem_base + half * 128 + cc * 32);
        asm volatile("tcgen05.wait::ld.sync.aligned;" ::: "memory");
        #pragma unroll
        for (int v = 0; v < 8; v++) {
            const float4 mv = mul4[cc * 8 + v];
            const float mvf[4] = {mv.x, mv.y, mv.z, mv.w};
            float o[4];
            #pragma unroll
            for (int e = 0; e < 4; e++) {
                const int j = v * 4 + e;
                const float x = __uint_as_float(d[j]) + __ldg(bias + n_base + cc * 32 + j);
                const float sg = 1.0f / (1.0f + __expf(-x));
                o[e] = x * sg * mvf[e];
            }
            out4[cc * 8 + v] = make_float4(o[0], o[1], o[2], o[3]);
        }
    }

    __syncthreads();
    if (wid == 0) {
        asm volatile("tcgen05.relinquish_alloc_permit.cta_group::2.sync.aligned;");
        asm volatile("tcgen05.dealloc.cta_group::2.sync.aligned.b32 %0, %1;"
                     :: "r"(tmem_base), "r"(256u));
    }
    CLUSTER_SYNC();   // no CTA exits while peer may still read its SMEM

#else
    // ------------------------------------------------------------- fallback path
    // Base compute_103 pass (never selected on sm_103a hardware; SASS exists).
    // Each CTA independently computes its 128(M) x 256(N) half of the pair tile
    // with legacy mma.sync; 4 stages of (A half 16KB + B full 32KB).
    const uint32_t rank_fb = cluster_rank();
    const int m_tile = pm * 2 + (int)rank_fb;

    const uint32_t FULL0 = LFULL0;       // count=1 (tx)
    const uint32_t EMP0  = EMPTY0;       // count=8 (per-warp arrive)

    if (tid == 0) {
        #pragma unroll
        for (int s = 0; s < FB_STAGES; s++) {
            MBAR_INIT(FULL0 + s * 8, 1);
            MBAR_INIT(EMP0 + s * 8, 8);
        }
        asm volatile("fence.proxy.async.shared::cta;" ::: "memory");
    }
    __syncthreads();

    const uint32_t data_off = data_base - smem_base;
    const int m0w = (wid >> 2) * 64;
    const int n0w = (wid & 3) * 64;

    float acc[4][8][4];
    #pragma unroll
    for (int mi = 0; mi < 4; mi++)
        #pragma unroll
        for (int ni = 0; ni < 8; ni++)
            #pragma unroll
            for (int e = 0; e < 4; e++) acc[mi][ni][e] = 0.0f;

    const char* a_src = reinterpret_cast<const char*>(g_As) +
                        (size_t)m_tile * K_CHUNKS * A_BLK_BYTES;
    const char* b_src = reinterpret_cast<const char*>(g_Ws) +
                        (size_t)n_tile * K_CHUNKS * B_BLK_BYTES;

    if (tid == 0) {
        #pragma unroll
        for (int j = 0; j < FB_STAGES - 1; j++) {
            const uint32_t fb = FULL0 + j * 8;
            MBAR_EXPECT_TX(fb, FB_STAGE_BYTES);
            bulk_g2s(data_base + j * FB_STAGE_BYTES, a_src + (size_t)j * A_BLK_BYTES,
                     A_BLK_BYTES, fb);
            bulk_g2s(data_base + j * FB_STAGE_BYTES + A_BLK_BYTES,
                     b_src + (size_t)j * B_BLK_BYTES, B_BLK_BYTES, fb);
        }
    }

    const int ar = lid >> 2;
    const int ac = lid & 3;

    #pragma unroll 1
    for (int it = 0; it < K_CHUNKS; it++) {
        const int s = it & 3;
        mbar_wait(FULL0 + s * 8, (it >> 2) & 1);

        const uint32_t a_base = data_off + s * FB_STAGE_BYTES;
        const uint32_t b_base = a_base + A_BLK_BYTES;

        #pragma unroll
        for (int ks = 0; ks < 4; ks++) {
            uint32_t afr[4][4];
            #pragma unroll
            for (int mi = 0; mi < 4; mi++) {
                const int r0 = m0w + mi * 16 + ar;
                const int c = ks * 8 + ac;
                afr[mi][0] = *(const uint32_t*)(smem + a_base + sw128(r0 * 128 + c * 4));
                afr[mi][1] = *(const uint32_t*)(smem + a_base + sw128((r0 + 8) * 128 + c * 4));
                afr[mi][2] = *(const uint32_t*)(smem + a_base + sw128(r0 * 128 + (c + 4) * 4));
                afr[mi][3] = *(const uint32_t*)(smem + a_base + sw128((r0 + 8) * 128 + (c + 4) * 4));
            }
            uint32_t bfr[8][2];
            #pragma unroll
            for (int ni = 0; ni < 8; ni++) {
                const int bn = n0w + ni * 8 + ar;
                const int bk = ks * 8 + ac;
                bfr[ni][0] = *(const uint32_t*)(smem + b_base + sw128(bn * 128 + bk * 4));
                bfr[ni][1] = *(const uint32_t*)(smem + b_base + sw128(bn * 128 + (bk + 4) * 4));
            }
            #pragma unroll
            for (int mi = 0; mi < 4; mi++)
                #pragma unroll
                for (int ni = 0; ni < 8; ni++)
                    mma_sync_tf32(acc[mi][ni], afr[mi], bfr[ni]);
        }

        if (lid == 0) MBAR_ARRIVE(EMP0 + s * 8);

        const int j = it + FB_STAGES - 1;
        if (j < K_CHUNKS && tid == 0) {
            const int s2 = j & 3;
            if (j >= FB_STAGES) mbar_wait(EMP0 + s2 * 8, ((j - FB_STAGES) >> 2) & 1);
            const uint32_t fb = FULL0 + s2 * 8;
            MBAR_EXPECT_TX(fb, FB_STAGE_BYTES);
            bulk_g2s(data_base + s2 * FB_STAGE_BYTES, a_src + (size_t)j * A_BLK_BYTES,
                     A_BLK_BYTES, fb);
            bulk_g2s(data_base + s2 * FB_STAGE_BYTES + A_BLK_BYTES,
                     b_src + (size_t)j * B_BLK_BYTES, B_BLK_BYTES, fb);
        }
    }

    const int gm0 = m_tile * 128 + m0w;
    const int gn0 = n_tile * 256 + n0w;
    #pragma unroll
    for (int mi = 0; mi < 4; mi++) {
        #pragma unroll
        for (int hrow = 0; hrow < 2; hrow++) {
            const int m = gm0 + mi * 16 + hrow * 8 + (lid >> 2);
            #pragma unroll
            for (int ni = 0; ni < 8; ni++) {
                const int n = gn0 + ni * 8 + (lid & 3) * 2;
                const float2 mv = *reinterpret_cast<const float2*>(mul + (size_t)m * N_DIM + n);
                float o[2];
                #pragma unroll
                for (int e = 0; e < 2; e++) {
                    const float x = acc[mi][ni][hrow * 2 + e] + __ldg(bias + n + e);
                    const float sg = 1.0f / (1.0f + __expf(-x));
                    o[e] = x * sg * ((e == 0) ? mv.x : mv.y);
                }
                *reinterpret_cast<float2*>(out + (size_t)m * N_DIM + n) = make_float2(o[0], o[1]);
            }
        }
    }
    CLUSTER_SYNC();
#endif
}

// ============================================================================
// Launch
// ============================================================================
extern "C" void kernel_launch(void* const* d_in, const int* in_sizes, int n_in,
                              void* d_out, int out_size) {
    const float* inp     = (const float*)d_in[0];
    const int*   qweight = (const int*)d_in[1];
    const float* scales  = (const float*)d_in[2];
    const int*   qzeros  = (const int*)d_in[3];
    const float* bias    = (const float*)d_in[4];
    const float* mul     = (const float*)d_in[5];
    float* out = (float*)d_out;

    cudaFuncSetAttribute(gemm_kernel, cudaFuncAttributeMaxDynamicSharedMemorySize,
                         GEMM_SMEM_BYTES);

    dequant_kernel<<<N_TILES * K_CHUNKS, 256>>>(qweight, scales, qzeros);
    aconv_kernel<<<M_TILES * K_CHUNKS, 256>>>(inp);

    cudaLaunchConfig_t cfg = {};
    cfg.gridDim = dim3(PAIR_M * N_TILES * 2, 1, 1);
    cfg.blockDim = dim3(256, 1, 1);
    cfg.dynamicSmemBytes = GEMM_SMEM_BYTES;
    cfg.stream = 0;
    cudaLaunchAttribute attr[1];
    attr[0].id = cudaLaunchAttributeClusterDimension;
    attr[0].val.clusterDim.x = 2;
    attr[0].val.clusterDim.y = 1;
    attr[0].val.clusterDim.z = 1;
    cfg.attrs = attr;
    cfg.numAttrs = 1;
    cudaLaunchKernelEx(&cfg, gemm_kernel, bias, mul, out);
}

// round 5
// speedup vs baseline: 2.1188x; 2.1188x over previous
#include <cuda_runtime.h>
#include <cstdint>
#include <cstddef>

// ============================================================================
// Arch feature detection: tcgen05 needs the 'a' target (sm_103a).
// The harness also builds a base compute_103 PTX pass -> guarded fallback.
// ============================================================================
#if defined(__CUDA_ARCH_FEAT_SM103_ALL) || defined(__CUDA_ARCH_FEAT_SM100_ALL) || defined(__CUDA_ARCH_FEAT_SM101_ALL)
#define HAS_TCGEN05 1
#else
#define HAS_TCGEN05 0
#endif

// ============================================================================
// Problem constants
// ============================================================================
#define M_DIM 4096
#define K_DIM 4096
#define N_DIM 11008
#define NW_TOT (N_DIM / 8)
#define GROUP 128

#define TILE_K 32                     // 32 tf32 = 128B = one SW128 row
#define K_CHUNKS (K_DIM / TILE_K)     // 128
#define M_TILES 32                    // 128-row A scratch blocks
#define N_TILES 43                    // 256-row W scratch blocks
#define M2_TILES 16                   // 256-row CTA tiles

#define A_BLK_BYTES (128 * TILE_K * 4)    // 16384 (one 128-row A block)
#define B_BLK_BYTES (256 * TILE_K * 4)    // 32768 (one 256-row W block)

// GEMM pipeline: stage = A0(16K) + A1(16K) + B(32K) = 64KB, 3 stages
#define STAGES 3
#define STAGE_BYTES (2 * A_BLK_BYTES + B_BLK_BYTES)   // 65536
#define GEMM_SMEM_BYTES (2048 + STAGES * STAGE_BYTES) // 198656

// fallback pipeline (base compute_103 pass only): stage = A half + B = 48KB, 4 stages
#define FB_STAGES 4
#define FB_STAGE_BYTES (A_BLK_BYTES + B_BLK_BYTES)    // 49152

// idesc kind::tf32 (cg1, M=128, N=256): dfmt=F32(1)<<4, a=TF32(2)<<7, b=TF32(2)<<10,
// N/8=32 @[17:23), M/16=8 @[24:29)
#define MMA_IDESC_TF32 ((1u << 4) | (2u << 7) | (2u << 10) | (32u << 17) | (8u << 24))

// Scratch: pre-tiled, pre-SW128-swizzled tf32 operands.
__device__ __align__(1024) float g_As[(size_t)M_TILES * K_CHUNKS * (128 * TILE_K)];
__device__ __align__(1024) float g_Ws[(size_t)N_TILES * K_CHUNKS * (256 * TILE_K)];

// ============================================================================
// Base-ISA helpers
// ============================================================================
__device__ __forceinline__ uint32_t smem_u32(const void* p) {
    uint32_t a;
    asm("{ .reg .u64 t; cvta.to.shared.u64 t, %1; cvt.u32.u64 %0, t; }" : "=r"(a) : "l"(p));
    return a;
}

__device__ __forceinline__ uint32_t sw128(uint32_t byte_off) {
    return byte_off ^ ((byte_off >> 3) & 0x70);
}

__device__ __forceinline__ uint32_t f2tf32(float v) {
    uint32_t r;
    asm("cvt.rna.tf32.f32 %0, %1;" : "=r"(r) : "f"(v));
    return r;
}

#define MBAR_INIT(addr, cnt) \
    asm volatile("mbarrier.init.shared.b64 [%0], %1;" :: "r"(addr), "r"((uint32_t)(cnt)) : "memory")

#define MBAR_EXPECT_TX(addr, bytes) \
    asm volatile("mbarrier.arrive.expect_tx.shared.b64 _, [%0], %1;" :: "r"(addr), "r"((uint32_t)(bytes)) : "memory")

#define MBAR_ARRIVE(addr) \
    asm volatile("mbarrier.arrive.release.cta.shared.b64 _, [%0];" :: "r"(addr) : "memory")

__device__ __forceinline__ void mbar_wait(uint32_t mbar, uint32_t parity) {
    uint32_t done;
    asm volatile(
        "{ .reg .pred p; mbarrier.try_wait.parity.acquire.cta.shared::cta.b64 p, [%1], %2; selp.b32 %0, 1, 0, p; }"
        : "=r"(done) : "r"(mbar), "r"(parity) : "memory");
    if (!done) {
        asm volatile(
            "{ .reg .pred P1;\n"
            "WL_%=: mbarrier.try_wait.parity.acquire.cta.shared::cta.b64 P1, [%0], %1, 0x989680;\n"
            "@P1 bra.uni WD_%=;\n"
            "bra.uni WL_%=;\n"
            "WD_%=: }"
            :: "r"(mbar), "r"(parity) : "memory");
    }
}

__device__ __forceinline__ void bulk_g2s(uint32_t dst_smem, const void* src_gmem,
                                         uint32_t bytes, uint32_t mbar) {
    asm volatile(
        "cp.async.bulk.shared::cluster.global.mbarrier::complete_tx::bytes [%0], [%1], %2, [%3];"
        :: "r"(dst_smem), "l"(src_gmem), "r"(bytes), "r"(mbar) : "memory");
}

// legacy tf32 mma (sm_80 base ISA) -- fallback path only
__device__ __forceinline__ void mma_sync_tf32(float* d, const uint32_t* a, const uint32_t* b) {
    asm volatile(
        "mma.sync.aligned.m16n8k8.row.col.f32.tf32.tf32.f32 "
        "{%0, %1, %2, %3}, {%4, %5, %6, %7}, {%8, %9}, {%0, %1, %2, %3};"
        : "+f"(d[0]), "+f"(d[1]), "+f"(d[2]), "+f"(d[3])
        : "r"(a[0]), "r"(a[1]), "r"(a[2]), "r"(a[3]), "r"(b[0]), "r"(b[1]));
}

#if HAS_TCGEN05
// ============================================================================
// sm_103a-only helpers
// ============================================================================
__device__ __forceinline__ uint32_t elect_one() {
    uint32_t p;
    asm volatile("{ .reg .pred p; elect.sync _|p, 0xFFFFFFFF; selp.b32 %0, 1, 0, p; }" : "=r"(p));
    return p;
}

__device__ __forceinline__ uint64_t make_desc_sw128(uint32_t addr) {
    const uint64_t base = (uint64_t(2) << 61) | (uint64_t(1) << 46) |
                          (uint64_t(64) << 32) | (uint64_t(1) << 16);
    return base | ((uint64_t)(addr >> 4) & 0x3FFF);
}

__device__ __forceinline__ void mma_tf32_ss(uint32_t d_tmem, uint64_t a_desc, uint64_t b_desc,
                                            uint32_t idesc, bool acc) {
    uint32_t en = acc ? 1u : 0u;
    asm volatile(
        "{\n\t"
        ".reg .pred p;\n\t"
        "setp.ne.u32 p, %5, 0;\n\t"
        "tcgen05.mma.cta_group::1.kind::tf32 [%0], %1, %2, %3, {%4, %4, %4, %4}, p;\n\t"
        "}"
        :: "r"(d_tmem), "l"(a_desc), "l"(b_desc), "r"(idesc), "r"(0u), "r"(en) : "memory");
}

#define TCGEN05_COMMIT(mbar) \
    asm volatile("tcgen05.commit.cta_group::1.mbarrier::arrive::one.shared::cluster.b64 [%0];" \
                 :: "r"(mbar) : "memory")

__device__ __forceinline__ void tcgen05_ld_x32(uint32_t* r, uint32_t tmem_addr) {
    asm volatile(
        "tcgen05.ld.sync.aligned.32x32b.x32.b32 "
        "{%0, %1, %2, %3, %4, %5, %6, %7, "
        " %8, %9, %10, %11, %12, %13, %14, %15, "
        " %16, %17, %18, %19, %20, %21, %22, %23, "
        " %24, %25, %26, %27, %28, %29, %30, %31}, [%32];"
        : "=r"(r[0]), "=r"(r[1]), "=r"(r[2]), "=r"(r[3]),
          "=r"(r[4]), "=r"(r[5]), "=r"(r[6]), "=r"(r[7]),
          "=r"(r[8]), "=r"(r[9]), "=r"(r[10]), "=r"(r[11]),
          "=r"(r[12]), "=r"(r[13]), "=r"(r[14]), "=r"(r[15]),
          "=r"(r[16]), "=r"(r[17]), "=r"(r[18]), "=r"(r[19]),
          "=r"(r[20]), "=r"(r[21]), "=r"(r[22]), "=r"(r[23]),
          "=r"(r[24]), "=r"(r[25]), "=r"(r[26]), "=r"(r[27]),
          "=r"(r[28]), "=r"(r[29]), "=r"(r[30]), "=r"(r[31])
        : "r"(tmem_addr));
}
#endif  // HAS_TCGEN05

// ============================================================================
// Kernel 1: dequantize int4 -> tf32, [N,K] pre-tiled + SW128-swizzled.
// SMEM-free value path (SW128 permutes 16B units; aligned uint4 STG lands right).
// ============================================================================
__global__ void __launch_bounds__(256) dequant_kernel(
    const int* __restrict__ qweight,
    const float* __restrict__ scales,
    const int* __restrict__ qzeros
) {
    const int bid = blockIdx.x;
    const int n_tile = bid >> 7;
    const int k_chunk = bid & 127;
    const int k0 = k_chunk * TILE_K;
    const int g = k0 >> 7;
    const int t = threadIdx.x;

    __shared__ uint32_t sq[TILE_K * 33];
    __shared__ uint32_t sz[32];

    {
        const int k = t >> 3;
        const int nw0 = (t & 7) * 4;
        const uint32_t* src = (const uint32_t*)qweight +
                              (size_t)(k0 + k) * NW_TOT + n_tile * 32 + nw0;
        #pragma unroll
        for (int i = 0; i < 4; i++) sq[k * 33 + nw0 + i] = src[i];
        if (t < 32) sz[t] = ((const uint32_t*)qzeros)[(size_t)g * NW_TOT + n_tile * 32 + t];
    }
    __syncthreads();

    char* dst_base = (char*)(g_Ws + (size_t)bid * (256 * TILE_K));
    #pragma unroll
    for (int p = 0; p < 8; p++) {
        const int idx = p * 256 + t;
        const int n_local = idx >> 3;
        const int u = idx & 7;
        const int nw = n_local >> 3;
        const int nib = (n_local & 7) * 4;
        const float z = (float)((sz[nw] >> nib) & 15u);
        const float s = __ldg(scales + (size_t)g * N_DIM + n_tile * 256 + n_local);
        uint32_t w[4];
        #pragma unroll
        for (int e = 0; e < 4; e++) {
            const float q = (float)((sq[(u * 4 + e) * 33 + nw] >> nib) & 15u);
            w[e] = f2tf32((q - z) * s);
        }
        *(uint4*)(dst_base + sw128((uint32_t)(n_local * 128 + u * 16))) =
            make_uint4(w[0], w[1], w[2], w[3]);
    }
}

// ============================================================================
// Kernel 2: activations fp32 -> tf32(RNA), SMEM-free, pre-tiled + swizzled
// ============================================================================
__global__ void __launch_bounds__(256) aconv_kernel(const float* __restrict__ inp) {
    const int bid = blockIdx.x;
    const int m_tile = bid >> 7;
    const int k_chunk = bid & 127;
    const size_t base_in = (size_t)(m_tile * 128) * K_DIM + k_chunk * TILE_K;
    char* dst_base = (char*)(g_As + (size_t)bid * (128 * TILE_K));
    const int t = threadIdx.x;

    #pragma unroll
    for (int p = 0; p < 4; p++) {
        const int idx = p * 256 + t;
        const int m_local = idx >> 3;
        const int u = idx & 7;
        const float4 f = *(const float4*)(inp + base_in + (size_t)m_local * K_DIM + u * 4);
        uint4 w = make_uint4(f2tf32(f.x), f2tf32(f.y), f2tf32(f.z), f2tf32(f.w));
        *(uint4*)(dst_base + sw128((uint32_t)(m_local * 128 + u * 16))) = w;
    }
}

// ============================================================================
// Kernel 3: single-CTA 256M x 256N GEMM. Two TMEM accumulators (D0/D1, 512
// TMEM cols), 8 mma dispatches per 32-K chunk sharing one B descriptor.
// 3-stage (64KB) bulk-copy pipeline driven by one elected thread.
// Fused bias + SiLU + mul epilogue. grid = 688, block = 256, no clusters.
// ============================================================================
__global__ void __launch_bounds__(256, 1) gemm_kernel(
    const float* __restrict__ bias,
    const float* __restrict__ mul,
    float* __restrict__ out
) {
    extern __shared__ char smem[];
    const uint32_t smem_base = smem_u32(smem);
    const uint32_t data_base = (smem_base + 128 + 1023) & ~1023u;

    const int tid = threadIdx.x;
    const int wid = tid >> 5;
    const int lid = tid & 31;
    const int bid = blockIdx.x;
    const int pm = bid & (M2_TILES - 1);   // m-fast: concurrent CTAs share B via L2
    const int n_tile = bid >> 4;

    const uint32_t FULL0  = smem_base + 8;    // 3 x 8B
    const uint32_t EMPTY0 = smem_base + 32;   // 3 x 8B
    const uint32_t DONE   = smem_base + 56;

#if HAS_TCGEN05
    if (wid == 0) {
        asm volatile("tcgen05.alloc.cta_group::1.sync.aligned.shared::cta.b32 [%0], %1;"
                     :: "r"(smem_base), "r"(512u) : "memory");
        asm volatile("tcgen05.relinquish_alloc_permit.cta_group::1.sync.aligned;");
    }
    if (tid == 0) {
        #pragma unroll
        for (int s = 0; s < STAGES; s++) {
            MBAR_INIT(FULL0 + s * 8, 1);
            MBAR_INIT(EMPTY0 + s * 8, 1);
        }
        MBAR_INIT(DONE, 1);
        asm volatile("fence.proxy.async.shared::cta;" ::: "memory");
    }
    __syncthreads();

    uint32_t tmem_base;
    asm volatile("ld.shared.b32 %0, [%1];" : "=r"(tmem_base) : "r"(smem_base));
    const uint32_t D0 = tmem_base;
    const uint32_t D1 = tmem_base + 256;

    if (wid == 0) {
        const uint32_t pred = elect_one();
        const char* a0_src = reinterpret_cast<const char*>(g_As) +
                             (size_t)(pm * 2) * K_CHUNKS * A_BLK_BYTES;
        const char* a1_src = a0_src + (size_t)K_CHUNKS * A_BLK_BYTES;
        const char* b_src  = reinterpret_cast<const char*>(g_Ws) +
                             (size_t)n_tile * K_CHUNKS * B_BLK_BYTES;

        if (pred) {
            // prologue: fill stages 0,1 with chunks 0,1
            #pragma unroll
            for (int j = 0; j < STAGES - 1; j++) {
                const uint32_t fb = FULL0 + j * 8;
                const uint32_t st = data_base + j * STAGE_BYTES;
                MBAR_EXPECT_TX(fb, STAGE_BYTES);
                bulk_g2s(st,                    a0_src + (size_t)j * A_BLK_BYTES, A_BLK_BYTES, fb);
                bulk_g2s(st + A_BLK_BYTES,      a1_src + (size_t)j * A_BLK_BYTES, A_BLK_BYTES, fb);
                bulk_g2s(st + 2 * A_BLK_BYTES,  b_src  + (size_t)j * B_BLK_BYTES, B_BLK_BYTES, fb);
            }

            // cursors (stage, phase) -- avoid div by 3 in the loop
            int fs = 0, fp = 0;      // FULL consume
            int rs = STAGES - 1;     // refill target stage (chunk j = it+2)
            int es = 0, ep = 0;      // EMPTY wait (refill gate, first used at j=3)

            #pragma unroll 1
            for (int it = 0; it < K_CHUNKS; it++) {
                mbar_wait(FULL0 + fs * 8, fp);
                {
                    const uint32_t st = data_base + fs * STAGE_BYTES;
                    const uint64_t a0d = make_desc_sw128(st);
                    const uint64_t a1d = make_desc_sw128(st + A_BLK_BYTES);
                    const uint64_t bd  = make_desc_sw128(st + 2 * A_BLK_BYTES);
                    #pragma unroll
                    for (int ks = 0; ks < 4; ks++) {
                        mma_tf32_ss(D0, a0d + ks * 2, bd + ks * 2, MMA_IDESC_TF32, (it | ks) != 0);
                        mma_tf32_ss(D1, a1d + ks * 2, bd + ks * 2, MMA_IDESC_TF32, (it | ks) != 0);
                    }
                    TCGEN05_COMMIT(EMPTY0 + fs * 8);
                }
                const int j = it + STAGES - 1;
                if (j < K_CHUNKS) {
                    if (j >= STAGES) {
                        mbar_wait(EMPTY0 + es * 8, ep);
                        if (++es == STAGES) { es = 0; ep ^= 1; }
                    }
                    const uint32_t fb = FULL0 + rs * 8;
                    const uint32_t st = data_base + rs * STAGE_BYTES;
                    MBAR_EXPECT_TX(fb, STAGE_BYTES);
                    bulk_g2s(st,                   a0_src + (size_t)j * A_BLK_BYTES, A_BLK_BYTES, fb);
                    bulk_g2s(st + A_BLK_BYTES,     a1_src + (size_t)j * A_BLK_BYTES, A_BLK_BYTES, fb);
                    bulk_g2s(st + 2 * A_BLK_BYTES, b_src  + (size_t)j * B_BLK_BYTES, B_BLK_BYTES, fb);
                    if (++rs == STAGES) rs = 0;
                }
                if (++fs == STAGES) { fs = 0; fp ^= 1; }
            }
            TCGEN05_COMMIT(DONE);
        }
        __syncwarp();
    }

    // ---------------- epilogue: 8 warps; warps 0-3 -> D0 rows, 4-7 -> D1 rows ----
    mbar_wait(DONE, 0);
    asm volatile("tcgen05.fence::after_thread_sync;" ::: "memory");

    const int mhalf = wid >> 2;                               // which 128-row half
    const uint32_t dbase = tmem_base + mhalf * 256;           // D0 or D1
    const int m = pm * 256 + mhalf * 128 + (wid & 3) * 32 + lid;
    const int n_base = n_tile * 256;
    const float4* mul4 = reinterpret_cast<const float4*>(mul + (size_t)m * N_DIM + n_base);
    float4* out4 = reinterpret_cast<float4*>(out + (size_t)m * N_DIM + n_base);

    #pragma unroll 1
    for (int cc = 0; cc < 8; cc++) {
        uint32_t d[32];
        tcgen05_ld_x32(d, dbase + cc * 32);
        asm volatile("tcgen05.wait::ld.sync.aligned;" ::: "memory");
        #pragma unroll
        for (int v = 0; v < 8; v++) {
            const float4 mv = mul4[cc * 8 + v];
            const float mvf[4] = {mv.x, mv.y, mv.z, mv.w};
            float o[4];
            #pragma unroll
            for (int e = 0; e < 4; e++) {
                const int j = v * 4 + e;
                const float x = __uint_as_float(d[j]) + __ldg(bias + n_base + cc * 32 + j);
                const float sg = 1.0f / (1.0f + __expf(-x));
                o[e] = x * sg * mvf[e];
            }
            out4[cc * 8 + v] = make_float4(o[0], o[1], o[2], o[3]);
        }
    }

    __syncthreads();
    if (wid == 0) {
        asm volatile("tcgen05.dealloc.cta_group::1.sync.aligned.b32 %0, %1;"
                     :: "r"(tmem_base), "r"(512u));
    }

#else
    // ------------------------------------------------------------- fallback path
    // Base compute_103 pass (never selected on sm_103a hardware; must compile).
    // Flat 256-iteration pipeline: j = mh*128 + it; A half per mh, B repeats.
    if (tid == 0) {
        #pragma unroll
        for (int s = 0; s < FB_STAGES; s++) {
            MBAR_INIT(FULL0 + s * 8, 1);
            MBAR_INIT(EMPTY0 + s * 8, 8);
        }
        asm volatile("fence.proxy.async.shared::cta;" ::: "memory");
    }
    __syncthreads();

    const uint32_t data_off = data_base - smem_base;
    const int m0w = (wid >> 2) * 64;
    const int n0w = (wid & 3) * 64;
    const int ar = lid >> 2;
    const int ac = lid & 3;

    const char* b_src = reinterpret_cast<const char*>(g_Ws) +
                        (size_t)n_tile * K_CHUNKS * B_BLK_BYTES;

    if (tid == 0) {
        #pragma unroll
        for (int j = 0; j < FB_STAGES - 1; j++) {
            const char* a_src = reinterpret_cast<const char*>(g_As) +
                                (size_t)(pm * 2 + (j >> 7)) * K_CHUNKS * A_BLK_BYTES;
            const uint32_t fb = FULL0 + (j & 3) * 8;
            MBAR_EXPECT_TX(fb, FB_STAGE_BYTES);
            bulk_g2s(data_base + (j & 3) * FB_STAGE_BYTES,
                     a_src + (size_t)(j & 127) * A_BLK_BYTES, A_BLK_BYTES, fb);
            bulk_g2s(data_base + (j & 3) * FB_STAGE_BYTES + A_BLK_BYTES,
                     b_src + (size_t)(j & 127) * B_BLK_BYTES, B_BLK_BYTES, fb);
        }
    }

    #pragma unroll 1
    for (int mh = 0; mh < 2; mh++) {
        float acc[4][8][4];
        #pragma unroll
        for (int mi = 0; mi < 4; mi++)
            #pragma unroll
            for (int ni = 0; ni < 8; ni++)
                #pragma unroll
                for (int e = 0; e < 4; e++) acc[mi][ni][e] = 0.0f;

        #pragma unroll 1
        for (int it = 0; it < K_CHUNKS; it++) {
            const int gj = mh * K_CHUNKS + it;
            const int s = gj & 3;
            mbar_wait(FULL0 + s * 8, (gj >> 2) & 1);

            const uint32_t a_base = data_off + s * FB_STAGE_BYTES;
            const uint32_t b_base = a_base + A_BLK_BYTES;

            #pragma unroll
            for (int ks = 0; ks < 4; ks++) {
                uint32_t afr[4][4];
                #pragma unroll
                for (int mi = 0; mi < 4; mi++) {
                    const int r0 = m0w + mi * 16 + ar;
                    const int c = ks * 8 + ac;
                    afr[mi][0] = *(const uint32_t*)(smem + a_base + sw128(r0 * 128 + c * 4));
                    afr[mi][1] = *(const uint32_t*)(smem + a_base + sw128((r0 + 8) * 128 + c * 4));
                    afr[mi][2] = *(const uint32_t*)(smem + a_base + sw128(r0 * 128 + (c + 4) * 4));
                    afr[mi][3] = *(const uint32_t*)(smem + a_base + sw128((r0 + 8) * 128 + (c + 4) * 4));
                }
                uint32_t bfr[8][2];
                #pragma unroll
                for (int ni = 0; ni < 8; ni++) {
                    const int bn = n0w + ni * 8 + ar;
                    const int bk = ks * 8 + ac;
                    bfr[ni][0] = *(const uint32_t*)(smem + b_base + sw128(bn * 128 + bk * 4));
                    bfr[ni][1] = *(const uint32_t*)(smem + b_base + sw128(bn * 128 + (bk + 4) * 4));
                }
                #pragma unroll
                for (int mi = 0; mi < 4; mi++)
                    #pragma unroll
                    for (int ni = 0; ni < 8; ni++)
                        mma_sync_tf32(acc[mi][ni], afr[mi], bfr[ni]);
            }

            if (lid == 0) MBAR_ARRIVE(EMPTY0 + s * 8);

            const int j = gj + FB_STAGES - 1;
            if (j < 2 * K_CHUNKS && tid == 0) {
                const int s2 = j & 3;
                if (j >= FB_STAGES) mbar_wait(EMPTY0 + s2 * 8, ((j - FB_STAGES) >> 2) & 1);
                const char* a_src = reinterpret_cast<const char*>(g_As) +
                                    (size_t)(pm * 2 + (j >> 7)) * K_CHUNKS * A_BLK_BYTES;
                const uint32_t fb = FULL0 + s2 * 8;
                MBAR_EXPECT_TX(fb, FB_STAGE_BYTES);
                bulk_g2s(data_base + s2 * FB_STAGE_BYTES,
                         a_src + (size_t)(j & 127) * A_BLK_BYTES, A_BLK_BYTES, fb);
                bulk_g2s(data_base + s2 * FB_STAGE_BYTES + A_BLK_BYTES,
                         b_src + (size_t)(j & 127) * B_BLK_BYTES, B_BLK_BYTES, fb);
            }
        }

        const int gm0 = pm * 256 + mh * 128 + m0w;
        const int gn0 = n_tile * 256 + n0w;
        #pragma unroll
        for (int mi = 0; mi < 4; mi++) {
            #pragma unroll
            for (int hrow = 0; hrow < 2; hrow++) {
                const int m = gm0 + mi * 16 + hrow * 8 + (lid >> 2);
                #pragma unroll
                for (int ni = 0; ni < 8; ni++) {
                    const int n = gn0 + ni * 8 + (lid & 3) * 2;
                    const float2 mv = *reinterpret_cast<const float2*>(mul + (size_t)m * N_DIM + n);
                    float o[2];
                    #pragma unroll
                    for (int e = 0; e < 2; e++) {
                        const float x = acc[mi][ni][hrow * 2 + e] + __ldg(bias + n + e);
                        const float sg = 1.0f / (1.0f + __expf(-x));
                        o[e] = x * sg * ((e == 0) ? mv.x : mv.y);
                    }
                    *reinterpret_cast<float2*>(out + (size_t)m * N_DIM + n) = make_float2(o[0], o[1]);
                }
            }
        }
    }
#endif
}

// ============================================================================
// Launch
// ============================================================================
extern "C" void kernel_launch(void* const* d_in, const int* in_sizes, int n_in,
                              void* d_out, int out_size) {
    const float* inp     = (const float*)d_in[0];
    const int*   qweight = (const int*)d_in[1];
    const float* scales  = (const float*)d_in[2];
    const int*   qzeros  = (const int*)d_in[3];
    const float* bias    = (const float*)d_in[4];
    const float* mul     = (const float*)d_in[5];
    float* out = (float*)d_out;

    cudaFuncSetAttribute(gemm_kernel, cudaFuncAttributeMaxDynamicSharedMemorySize,
                         GEMM_SMEM_BYTES);

    dequant_kernel<<<N_TILES * K_CHUNKS, 256>>>(qweight, scales, qzeros);
    aconv_kernel<<<M_TILES * K_CHUNKS, 256>>>(inp);
    gemm_kernel<<<M2_TILES * N_TILES, 256, GEMM_SMEM_BYTES>>>(bias, mul, out);
}

// round 6
// speedup vs baseline: 2.8797x; 1.3591x over previous
#include <cuda_runtime.h>
#include <cuda_fp16.h>
#include <cstdint>
#include <cstddef>

// ============================================================================
// Arch feature detection: tcgen05 needs the 'a' target (sm_103a).
// The harness also builds a base compute_103 PTX pass -> guarded fallback.
// ============================================================================
#if defined(__CUDA_ARCH_FEAT_SM103_ALL) || defined(__CUDA_ARCH_FEAT_SM100_ALL) || defined(__CUDA_ARCH_FEAT_SM101_ALL)
#define HAS_TCGEN05 1
#else
#define HAS_TCGEN05 0
#endif

// ============================================================================
// Problem constants
// ============================================================================
#define M_DIM 4096
#define K_DIM 4096
#define N_DIM 11008
#define NW_TOT (N_DIM / 8)
#define GROUP 128

#define TILE_K 64                     // 64 fp16 = 128B = one SW128 row
#define K_CHUNKS (K_DIM / TILE_K)     // 64
#define M_TILES 32                    // 128-row A scratch blocks
#define N_TILES 43                    // 256-row W scratch blocks
#define M2_TILES 16                   // 256-row CTA tiles

#define A_BLK_BYTES (128 * TILE_K * 2)    // 16384
#define B_BLK_BYTES (256 * TILE_K * 2)    // 32768

// GEMM pipeline: stage = A0(16K) + A1(16K) + B(32K) = 64KB, 3 stages
#define STAGES 3
#define STAGE_BYTES (2 * A_BLK_BYTES + B_BLK_BYTES)   // 65536
#define GEMM_SMEM_BYTES (2048 + STAGES * STAGE_BYTES) // 198656

// fallback pipeline (base compute_103 pass only): stage = A half + B = 48KB
#define FB_STAGES 4
#define FB_STAGE_BYTES (A_BLK_BYTES + B_BLK_BYTES)    // 49152

// idesc kind::f16, fp16 a/b, fp32 d (cg1, M=128, N=256):
// dfmt=F32(1)<<4, atype=FP16(0)<<7, btype=FP16(0)<<10, N/8=32 @[17:23), M/16=8 @[24:29)
#define MMA_IDESC_F16 ((1u << 4) | (32u << 17) | (8u << 24))

// Scratch: pre-tiled, pre-SW128-swizzled fp16 operands.
__device__ __align__(1024) uint16_t g_As[(size_t)M_TILES * K_CHUNKS * (128 * TILE_K)];
__device__ __align__(1024) uint16_t g_Ws[(size_t)N_TILES * K_CHUNKS * (256 * TILE_K)];

// ============================================================================
// Base-ISA helpers
// ============================================================================
__device__ __forceinline__ uint32_t smem_u32(const void* p) {
    uint32_t a;
    asm("{ .reg .u64 t; cvta.to.shared.u64 t, %1; cvt.u32.u64 %0, t; }" : "=r"(a) : "l"(p));
    return a;
}

__device__ __forceinline__ uint32_t sw128(uint32_t byte_off) {
    return byte_off ^ ((byte_off >> 3) & 0x70);
}

// pack two fp32 -> half2 (rn)
__device__ __forceinline__ uint32_t pack_h2(float a, float b) {
    uint32_t r;
    asm("{ .reg .f16 lo, hi;\n"
        "cvt.rn.f16.f32 lo, %1;\n"
        "cvt.rn.f16.f32 hi, %2;\n"
        "mov.b32 %0, {lo, hi}; }"
        : "=r"(r) : "f"(a), "f"(b));
    return r;
}

#define MBAR_INIT(addr, cnt) \
    asm volatile("mbarrier.init.shared.b64 [%0], %1;" :: "r"(addr), "r"((uint32_t)(cnt)) : "memory")

#define MBAR_EXPECT_TX(addr, bytes) \
    asm volatile("mbarrier.arrive.expect_tx.shared.b64 _, [%0], %1;" :: "r"(addr), "r"((uint32_t)(bytes)) : "memory")

#define MBAR_ARRIVE(addr) \
    asm volatile("mbarrier.arrive.release.cta.shared.b64 _, [%0];" :: "r"(addr) : "memory")

__device__ __forceinline__ void mbar_wait(uint32_t mbar, uint32_t parity) {
    uint32_t done;
    asm volatile(
        "{ .reg .pred p; mbarrier.try_wait.parity.acquire.cta.shared::cta.b64 p, [%1], %2; selp.b32 %0, 1, 0, p; }"
        : "=r"(done) : "r"(mbar), "r"(parity) : "memory");
    if (!done) {
        asm volatile(
            "{ .reg .pred P1;\n"
            "WL_%=: mbarrier.try_wait.parity.acquire.cta.shared::cta.b64 P1, [%0], %1, 0x989680;\n"
            "@P1 bra.uni WD_%=;\n"
            "bra.uni WL_%=;\n"
            "WD_%=: }"
            :: "r"(mbar), "r"(parity) : "memory");
    }
}

__device__ __forceinline__ void bulk_g2s(uint32_t dst_smem, const void* src_gmem,
                                         uint32_t bytes, uint32_t mbar) {
    asm volatile(
        "cp.async.bulk.shared::cluster.global.mbarrier::complete_tx::bytes [%0], [%1], %2, [%3];"
        :: "r"(dst_smem), "l"(src_gmem), "r"(bytes), "r"(mbar) : "memory");
}

// legacy f16 mma (sm_80 base ISA) -- fallback path only
__device__ __forceinline__ void mma_sync_f16(float* d, const uint32_t* a, const uint32_t* b) {
    asm volatile(
        "mma.sync.aligned.m16n8k16.row.col.f32.f16.f16.f32 "
        "{%0, %1, %2, %3}, {%4, %5, %6, %7}, {%8, %9}, {%0, %1, %2, %3};"
        : "+f"(d[0]), "+f"(d[1]), "+f"(d[2]), "+f"(d[3])
        : "r"(a[0]), "r"(a[1]), "r"(a[2]), "r"(a[3]), "r"(b[0]), "r"(b[1]));
}

#if HAS_TCGEN05
// ============================================================================
// sm_103a-only helpers
// ============================================================================
__device__ __forceinline__ uint32_t elect_one() {
    uint32_t p;
    asm volatile("{ .reg .pred p; elect.sync _|p, 0xFFFFFFFF; selp.b32 %0, 1, 0, p; }" : "=r"(p));
    return p;
}

__device__ __forceinline__ uint64_t make_desc_sw128(uint32_t addr) {
    const uint64_t base = (uint64_t(2) << 61) | (uint64_t(1) << 46) |
                          (uint64_t(64) << 32) | (uint64_t(1) << 16);
    return base | ((uint64_t)(addr >> 4) & 0x3FFF);
}

__device__ __forceinline__ void mma_f16_ss(uint32_t d_tmem, uint64_t a_desc, uint64_t b_desc,
                                           uint32_t idesc, bool acc) {
    uint32_t en = acc ? 1u : 0u;
    asm volatile(
        "{\n\t"
        ".reg .pred p;\n\t"
        "setp.ne.u32 p, %5, 0;\n\t"
        "tcgen05.mma.cta_group::1.kind::f16 [%0], %1, %2, %3, {%4, %4, %4, %4}, p;\n\t"
        "}"
        :: "r"(d_tmem), "l"(a_desc), "l"(b_desc), "r"(idesc), "r"(0u), "r"(en) : "memory");
}

#define TCGEN05_COMMIT(mbar) \
    asm volatile("tcgen05.commit.cta_group::1.mbarrier::arrive::one.shared::cluster.b64 [%0];" \
                 :: "r"(mbar) : "memory")

__device__ __forceinline__ void tcgen05_ld_x32(uint32_t* r, uint32_t tmem_addr) {
    asm volatile(
        "tcgen05.ld.sync.aligned.32x32b.x32.b32 "
        "{%0, %1, %2, %3, %4, %5, %6, %7, "
        " %8, %9, %10, %11, %12, %13, %14, %15, "
        " %16, %17, %18, %19, %20, %21, %22, %23, "
        " %24, %25, %26, %27, %28, %29, %30, %31}, [%32];"
        : "=r"(r[0]), "=r"(r[1]), "=r"(r[2]), "=r"(r[3]),
          "=r"(r[4]), "=r"(r[5]), "=r"(r[6]), "=r"(r[7]),
          "=r"(r[8]), "=r"(r[9]), "=r"(r[10]), "=r"(r[11]),
          "=r"(r[12]), "=r"(r[13]), "=r"(r[14]), "=r"(r[15]),
          "=r"(r[16]), "=r"(r[17]), "=r"(r[18]), "=r"(r[19]),
          "=r"(r[20]), "=r"(r[21]), "=r"(r[22]), "=r"(r[23]),
          "=r"(r[24]), "=r"(r[25]), "=r"(r[26]), "=r"(r[27]),
          "=r"(r[28]), "=r"(r[29]), "=r"(r[30]), "=r"(r[31])
        : "r"(tmem_addr));
}
#endif  // HAS_TCGEN05

// ============================================================================
// Kernel 1: dequantize int4 -> fp16, [N,K] pre-tiled + SW128-swizzled.
// SMEM-free value path: each 16B unit = 8 consecutive K halves of one N row.
// grid = N_TILES * K_CHUNKS (2752), block = 256.
// ============================================================================
__global__ void __launch_bounds__(256) dequant_kernel(
    const int* __restrict__ qweight,
    const float* __restrict__ scales,
    const int* __restrict__ qzeros
) {
    const int bid = blockIdx.x;
    const int n_tile = bid >> 6;
    const int k_chunk = bid & 63;
    const int k0 = k_chunk * TILE_K;
    const int g = k0 >> 7;               // 64-K chunk never crosses a 128 group
    const int t = threadIdx.x;

    __shared__ uint32_t sq[TILE_K * 33];  // [k][nw], stride 33
    __shared__ uint32_t sz[32];

    {
        const int k = t >> 2;             // 0..63
        const int nw0 = (t & 3) * 8;      // 0,8,16,24
        const uint32_t* src = (const uint32_t*)qweight +
                              (size_t)(k0 + k) * NW_TOT + n_tile * 32 + nw0;
        #pragma unroll
        for (int i = 0; i < 8; i++) sq[k * 33 + nw0 + i] = src[i];
        if (t < 32) sz[t] = ((const uint32_t*)qzeros)[(size_t)g * NW_TOT + n_tile * 32 + t];
    }
    __syncthreads();

    char* dst_base = (char*)(g_Ws + (size_t)bid * (256 * TILE_K));
    #pragma unroll
    for (int p = 0; p < 8; p++) {
        const int idx = p * 256 + t;
        const int n_local = idx >> 3;        // 0..255
        const int u = idx & 7;               // 16B unit = 8 K halves
        const int nw = n_local >> 3;
        const int nib = (n_local & 7) * 4;
        const float z = (float)((sz[nw] >> nib) & 15u);
        const float s = __ldg(scales + (size_t)g * N_DIM + n_tile * 256 + n_local);
        float w[8];
        #pragma unroll
        for (int e = 0; e < 8; e++) {
            const float q = (float)((sq[(u * 8 + e) * 33 + nw] >> nib) & 15u);
            w[e] = (q - z) * s;
        }
        *(uint4*)(dst_base + sw128((uint32_t)(n_local * 128 + u * 16))) =
            make_uint4(pack_h2(w[0], w[1]), pack_h2(w[2], w[3]),
                       pack_h2(w[4], w[5]), pack_h2(w[6], w[7]));
    }
}

// ============================================================================
// Kernel 2: activations fp32 -> fp16(rn), SMEM-free, pre-tiled + swizzled.
// grid = M_TILES * K_CHUNKS (2048), block = 256.
// ============================================================================
__global__ void __launch_bounds__(256) aconv_kernel(const float* __restrict__ inp) {
    const int bid = blockIdx.x;
    const int m_tile = bid >> 6;
    const int k_chunk = bid & 63;
    const size_t base_in = (size_t)(m_tile * 128) * K_DIM + k_chunk * TILE_K;
    char* dst_base = (char*)(g_As + (size_t)bid * (128 * TILE_K));
    const int t = threadIdx.x;

    #pragma unroll
    for (int p = 0; p < 4; p++) {
        const int idx = p * 256 + t;
        const int m_local = idx >> 3;        // 0..127
        const int u = idx & 7;               // 8 K halves per unit
        const float4* src = (const float4*)(inp + base_in + (size_t)m_local * K_DIM + u * 8);
        const float4 f0 = src[0];
        const float4 f1 = src[1];
        *(uint4*)(dst_base + sw128((uint32_t)(m_local * 128 + u * 16))) =
            make_uint4(pack_h2(f0.x, f0.y), pack_h2(f0.z, f0.w),
                       pack_h2(f1.x, f1.y), pack_h2(f1.z, f1.w));
    }
}

// ============================================================================
// Kernel 3: single-CTA 256M x 256N fp16 GEMM. Two TMEM accumulators (512 cols),
// 8 mma dispatches per 64-K chunk sharing one B descriptor. 3-stage (64KB)
// bulk-copy pipeline. Fused bias + SiLU + mul epilogue. grid = 688, block = 256.
// ============================================================================
__global__ void __launch_bounds__(256, 1) gemm_kernel(
    const float* __restrict__ bias,
    const float* __restrict__ mul,
    float* __restrict__ out
) {
    extern __shared__ char smem[];
    const uint32_t smem_base = smem_u32(smem);
    const uint32_t data_base = (smem_base + 128 + 1023) & ~1023u;

    const int tid = threadIdx.x;
    const int wid = tid >> 5;
    const int lid = tid & 31;
    const int bid = blockIdx.x;
    const int pm = bid & (M2_TILES - 1);   // m-fast: concurrent CTAs share B via L2
    const int n_tile = bid >> 4;

    const uint32_t FULL0  = smem_base + 8;    // 3 x 8B
    const uint32_t EMPTY0 = smem_base + 32;   // 3 x 8B
    const uint32_t DONE   = smem_base + 56;

#if HAS_TCGEN05
    if (wid == 0) {
        asm volatile("tcgen05.alloc.cta_group::1.sync.aligned.shared::cta.b32 [%0], %1;"
                     :: "r"(smem_base), "r"(512u) : "memory");
        asm volatile("tcgen05.relinquish_alloc_permit.cta_group::1.sync.aligned;");
    }
    if (tid == 0) {
        #pragma unroll
        for (int s = 0; s < STAGES; s++) {
            MBAR_INIT(FULL0 + s * 8, 1);
            MBAR_INIT(EMPTY0 + s * 8, 1);
        }
        MBAR_INIT(DONE, 1);
        asm volatile("fence.proxy.async.shared::cta;" ::: "memory");
    }
    __syncthreads();

    uint32_t tmem_base;
    asm volatile("ld.shared.b32 %0, [%1];" : "=r"(tmem_base) : "r"(smem_base));
    const uint32_t D0 = tmem_base;
    const uint32_t D1 = tmem_base + 256;

    if (wid == 0) {
        const uint32_t pred = elect_one();
        const char* a0_src = reinterpret_cast<const char*>(g_As) +
                             (size_t)(pm * 2) * K_CHUNKS * A_BLK_BYTES;
        const char* a1_src = a0_src + (size_t)K_CHUNKS * A_BLK_BYTES;
        const char* b_src  = reinterpret_cast<const char*>(g_Ws) +
                             (size_t)n_tile * K_CHUNKS * B_BLK_BYTES;

        if (pred) {
            #pragma unroll
            for (int j = 0; j < STAGES - 1; j++) {
                const uint32_t fb = FULL0 + j * 8;
                const uint32_t st = data_base + j * STAGE_BYTES;
                MBAR_EXPECT_TX(fb, STAGE_BYTES);
                bulk_g2s(st,                    a0_src + (size_t)j * A_BLK_BYTES, A_BLK_BYTES, fb);
                bulk_g2s(st + A_BLK_BYTES,      a1_src + (size_t)j * A_BLK_BYTES, A_BLK_BYTES, fb);
                bulk_g2s(st + 2 * A_BLK_BYTES,  b_src  + (size_t)j * B_BLK_BYTES, B_BLK_BYTES, fb);
            }

            int fs = 0, fp = 0;      // FULL consume cursor
            int rs = STAGES - 1;     // refill stage cursor
            int es = 0, ep = 0;      // EMPTY wait cursor

            #pragma unroll 1
            for (int it = 0; it < K_CHUNKS; it++) {
                mbar_wait(FULL0 + fs * 8, fp);
                {
                    const uint32_t st = data_base + fs * STAGE_BYTES;
                    const uint64_t a0d = make_desc_sw128(st);
                    const uint64_t a1d = make_desc_sw128(st + A_BLK_BYTES);
                    const uint64_t bd  = make_desc_sw128(st + 2 * A_BLK_BYTES);
                    #pragma unroll
                    for (int ks = 0; ks < 4; ks++) {   // 4 x K=16 fp16 steps = 64 K
                        mma_f16_ss(D0, a0d + ks * 2, bd + ks * 2, MMA_IDESC_F16, (it | ks) != 0);
                        mma_f16_ss(D1, a1d + ks * 2, bd + ks * 2, MMA_IDESC_F16, (it | ks) != 0);
                    }
                    TCGEN05_COMMIT(EMPTY0 + fs * 8);
                }
                const int j = it + STAGES - 1;
                if (j < K_CHUNKS) {
                    if (j >= STAGES) {
                        mbar_wait(EMPTY0 + es * 8, ep);
                        if (++es == STAGES) { es = 0; ep ^= 1; }
                    }
                    const uint32_t fb = FULL0 + rs * 8;
                    const uint32_t st = data_base + rs * STAGE_BYTES;
                    MBAR_EXPECT_TX(fb, STAGE_BYTES);
                    bulk_g2s(st,                   a0_src + (size_t)j * A_BLK_BYTES, A_BLK_BYTES, fb);
                    bulk_g2s(st + A_BLK_BYTES,     a1_src + (size_t)j * A_BLK_BYTES, A_BLK_BYTES, fb);
                    bulk_g2s(st + 2 * A_BLK_BYTES, b_src  + (size_t)j * B_BLK_BYTES, B_BLK_BYTES, fb);
                    if (++rs == STAGES) rs = 0;
                }
                if (++fs == STAGES) { fs = 0; fp ^= 1; }
            }
            TCGEN05_COMMIT(DONE);
        }
        __syncwarp();
    }

    // ---------------- epilogue: 8 warps; warps 0-3 -> D0 rows, 4-7 -> D1 rows ----
    mbar_wait(DONE, 0);
    asm volatile("tcgen05.fence::after_thread_sync;" ::: "memory");

    const int mhalf = wid >> 2;
    const uint32_t dbase = tmem_base + mhalf * 256;
    const int m = pm * 256 + mhalf * 128 + (wid & 3) * 32 + lid;
    const int n_base = n_tile * 256;
    const float4* mul4 = reinterpret_cast<const float4*>(mul + (size_t)m * N_DIM + n_base);
    float4* out4 = reinterpret_cast<float4*>(out + (size_t)m * N_DIM + n_base);

    #pragma unroll 1
    for (int cc = 0; cc < 8; cc++) {
        uint32_t d[32];
        tcgen05_ld_x32(d, dbase + cc * 32);
        asm volatile("tcgen05.wait::ld.sync.aligned;" ::: "memory");
        #pragma unroll
        for (int v = 0; v < 8; v++) {
            const float4 mv = mul4[cc * 8 + v];
            const float mvf[4] = {mv.x, mv.y, mv.z, mv.w};
            float o[4];
            #pragma unroll
            for (int e = 0; e < 4; e++) {
                const int j = v * 4 + e;
                const float x = __uint_as_float(d[j]) + __ldg(bias + n_base + cc * 32 + j);
                const float sg = 1.0f / (1.0f + __expf(-x));
                o[e] = x * sg * mvf[e];
            }
            out4[cc * 8 + v] = make_float4(o[0], o[1], o[2], o[3]);
        }
    }

    __syncthreads();
    if (wid == 0) {
        asm volatile("tcgen05.dealloc.cta_group::1.sync.aligned.b32 %0, %1;"
                     :: "r"(tmem_base), "r"(512u));
    }

#else
    // ------------------------------------------------------------- fallback path
    // Base compute_103 pass (never selected on sm_103a hardware; must compile).
    // m16n8k16 f16 mma; flat 128-iteration pipeline: j = mh*64 + it.
    if (tid == 0) {
        #pragma unroll
        for (int s = 0; s < FB_STAGES; s++) {
            MBAR_INIT(FULL0 + s * 8, 1);
            MBAR_INIT(EMPTY0 + s * 8, 8);
        }
        asm volatile("fence.proxy.async.shared::cta;" ::: "memory");
    }
    __syncthreads();

    const uint32_t data_off = data_base - smem_base;
    const int m0w = (wid >> 2) * 64;
    const int n0w = (wid & 3) * 64;
    const int ar = lid >> 2;
    const int ac = lid & 3;

    const char* b_src = reinterpret_cast<const char*>(g_Ws) +
                        (size_t)n_tile * K_CHUNKS * B_BLK_BYTES;

    if (tid == 0) {
        #pragma unroll
        for (int j = 0; j < FB_STAGES - 1; j++) {
            const char* a_src = reinterpret_cast<const char*>(g_As) +
                                (size_t)(pm * 2 + (j >> 6)) * K_CHUNKS * A_BLK_BYTES;
            const uint32_t fb = FULL0 + (j & 3) * 8;
            MBAR_EXPECT_TX(fb, FB_STAGE_BYTES);
            bulk_g2s(data_base + (j & 3) * FB_STAGE_BYTES,
                     a_src + (size_t)(j & 63) * A_BLK_BYTES, A_BLK_BYTES, fb);
            bulk_g2s(data_base + (j & 3) * FB_STAGE_BYTES + A_BLK_BYTES,
                     b_src + (size_t)(j & 63) * B_BLK_BYTES, B_BLK_BYTES, fb);
        }
    }

    #pragma unroll 1
    for (int mh = 0; mh < 2; mh++) {
        float acc[4][8][4];
        #pragma unroll
        for (int mi = 0; mi < 4; mi++)
            #pragma unroll
            for (int ni = 0; ni < 8; ni++)
                #pragma unroll
                for (int e = 0; e < 4; e++) acc[mi][ni][e] = 0.0f;

        #pragma unroll 1
        for (int it = 0; it < K_CHUNKS; it++) {
            const int gj = mh * K_CHUNKS + it;
            const int s = gj & 3;
            mbar_wait(FULL0 + s * 8, (gj >> 2) & 1);

            const uint32_t a_base = data_off + s * FB_STAGE_BYTES;
            const uint32_t b_base = a_base + A_BLK_BYTES;

            #pragma unroll
            for (int ks = 0; ks < 4; ks++) {       // 4 x K=16 per 64-K chunk
                uint32_t afr[4][4];
                #pragma unroll
                for (int mi = 0; mi < 4; mi++) {
                    const int r0 = m0w + mi * 16 + ar;
                    const int c = ks * 16 + ac * 2;            // fp16 col
                    afr[mi][0] = *(const uint32_t*)(smem + a_base + sw128(r0 * 128 + c * 2));
                    afr[mi][1] = *(const uint32_t*)(smem + a_base + sw128((r0 + 8) * 128 + c * 2));
                    afr[mi][2] = *(const uint32_t*)(smem + a_base + sw128(r0 * 128 + (c + 8) * 2));
                    afr[mi][3] = *(const uint32_t*)(smem + a_base + sw128((r0 + 8) * 128 + (c + 8) * 2));
                }
                uint32_t bfr[8][2];
                #pragma unroll
                for (int ni = 0; ni < 8; ni++) {
                    const int bn = n0w + ni * 8 + ar;
                    const int bk = ks * 16 + ac * 2;
                    bfr[ni][0] = *(const uint32_t*)(smem + b_base + sw128(bn * 128 + bk * 2));
                    bfr[ni][1] = *(const uint32_t*)(smem + b_base + sw128(bn * 128 + (bk + 8) * 2));
                }
                #pragma unroll
                for (int mi = 0; mi < 4; mi++)
                    #pragma unroll
                    for (int ni = 0; ni < 8; ni++)
                        mma_sync_f16(acc[mi][ni], afr[mi], bfr[ni]);
            }

            if (lid == 0) MBAR_ARRIVE(EMPTY0 + s * 8);

            const int j = gj + FB_STAGES - 1;
            if (j < 2 * K_CHUNKS && tid == 0) {
                const int s2 = j & 3;
                if (j >= FB_STAGES) mbar_wait(EMPTY0 + s2 * 8, ((j - FB_STAGES) >> 2) & 1);
                const char* a_src = reinterpret_cast<const char*>(g_As) +
                                    (size_t)(pm * 2 + (j >> 6)) * K_CHUNKS * A_BLK_BYTES;
                const uint32_t fb = FULL0 + s2 * 8;
                MBAR_EXPECT_TX(fb, FB_STAGE_BYTES);
                bulk_g2s(data_base + s2 * FB_STAGE_BYTES,
                         a_src + (size_t)(j & 63) * A_BLK_BYTES, A_BLK_BYTES, fb);
                bulk_g2s(data_base + s2 * FB_STAGE_BYTES + A_BLK_BYTES,
                         b_src + (size_t)(j & 63) * B_BLK_BYTES, B_BLK_BYTES, fb);
            }
        }

        const int gm0 = pm * 256 + mh * 128 + m0w;
        const int gn0 = n_tile * 256 + n0w;
        #pragma unroll
        for (int mi = 0; mi < 4; mi++) {
            #pragma unroll
            for (int hrow = 0; hrow < 2; hrow++) {
                const int m = gm0 + mi * 16 + hrow * 8 + (lid >> 2);
                #pragma unroll
                for (int ni = 0; ni < 8; ni++) {
                    const int n = gn0 + ni * 8 + (lid & 3) * 2;
                    const float2 mv = *reinterpret_cast<const float2*>(mul + (size_t)m * N_DIM + n);
                    float o[2];
                    #pragma unroll
                    for (int e = 0; e < 2; e++) {
                        const float x = acc[mi][ni][hrow * 2 + e] + __ldg(bias + n + e);
                        const float sg = 1.0f / (1.0f + __expf(-x));
                        o[e] = x * sg * ((e == 0) ? mv.x : mv.y);
                    }
                    *reinterpret_cast<float2*>(out + (size_t)m * N_DIM + n) = make_float2(o[0], o[1]);
                }
            }
        }
    }
#endif
}

// ============================================================================
// Launch
// ============================================================================
extern "C" void kernel_launch(void* const* d_in, const int* in_sizes, int n_in,
                              void* d_out, int out_size) {
    const float* inp     = (const float*)d_in[0];
    const int*   qweight = (const int*)d_in[1];
    const float* scales  = (const float*)d_in[2];
    const int*   qzeros  = (const int*)d_in[3];
    const float* bias    = (const float*)d_in[4];
    const float* mul     = (const float*)d_in[5];
    float* out = (float*)d_out;

    cudaFuncSetAttribute(gemm_kernel, cudaFuncAttributeMaxDynamicSharedMemorySize,
                         GEMM_SMEM_BYTES);

    dequant_kernel<<<N_TILES * K_CHUNKS, 256>>>(qweight, scales, qzeros);
    aconv_kernel<<<M_TILES * K_CHUNKS, 256>>>(inp);
    gemm_kernel<<<M2_TILES * N_TILES, 256, GEMM_SMEM_BYTES>>>(bias, mul, out);
}

// round 7
// speedup vs baseline: 2.9993x; 1.0415x over previous
#include <cuda_runtime.h>
#include <cuda_fp16.h>
#include <cstdint>
#include <cstddef>

// ============================================================================
// Arch feature detection: tcgen05 needs the 'a' target (sm_103a).
// The harness also builds a base compute_103 PTX pass -> guarded fallback.
// ============================================================================
#if defined(__CUDA_ARCH_FEAT_SM103_ALL) || defined(__CUDA_ARCH_FEAT_SM100_ALL) || defined(__CUDA_ARCH_FEAT_SM101_ALL)
#define HAS_TCGEN05 1
#else
#define HAS_TCGEN05 0
#endif

// ============================================================================
// Problem constants
// ============================================================================
#define M_DIM 4096
#define K_DIM 4096
#define N_DIM 11008
#define NW_TOT (N_DIM / 8)
#define GROUP 128

#define TILE_K 64                     // 64 fp16 = 128B = one SW128 row
#define K_CHUNKS (K_DIM / TILE_K)     // 64
#define M_TILES 32                    // 128-row A scratch blocks
#define N_TILES 43                    // 256-row W scratch blocks
#define M2_TILES 16                   // 256-row CTA tiles

#define A_BLK_BYTES (128 * TILE_K * 2)    // 16384
#define B_BLK_BYTES (256 * TILE_K * 2)    // 32768

// GEMM pipeline: stage = A0(16K) + A1(16K) + B(32K) = 64KB, 3 stages
#define STAGES 3
#define STAGE_BYTES (2 * A_BLK_BYTES + B_BLK_BYTES)   // 65536
#define GEMM_SMEM_BYTES (2048 + STAGES * STAGE_BYTES) // 198656

// fallback pipeline (base compute_103 pass only): stage = A half + B = 48KB
#define FB_STAGES 4
#define FB_STAGE_BYTES (A_BLK_BYTES + B_BLK_BYTES)    // 49152

// fused prep kernel block ranges
#define DQ_BLOCKS (N_TILES * K_CHUNKS)     // 2752
#define AC_BLOCKS (M_TILES * K_CHUNKS)     // 2048

// idesc kind::f16, fp16 a/b, fp32 d (cg1, M=128, N=256):
// dfmt=F32(1)<<4, atype=FP16(0)<<7, btype=FP16(0)<<10, N/8=32 @[17:23), M/16=8 @[24:29)
#define MMA_IDESC_F16 ((1u << 4) | (32u << 17) | (8u << 24))

// Scratch: pre-tiled, pre-SW128-swizzled fp16 operands.
__device__ __align__(1024) uint16_t g_As[(size_t)M_TILES * K_CHUNKS * (128 * TILE_K)];
__device__ __align__(1024) uint16_t g_Ws[(size_t)N_TILES * K_CHUNKS * (256 * TILE_K)];

// ============================================================================
// Base-ISA helpers
// ============================================================================
__device__ __forceinline__ uint32_t smem_u32(const void* p) {
    uint32_t a;
    asm("{ .reg .u64 t; cvta.to.shared.u64 t, %1; cvt.u32.u64 %0, t; }" : "=r"(a) : "l"(p));
    return a;
}

__device__ __forceinline__ uint32_t sw128(uint32_t byte_off) {
    return byte_off ^ ((byte_off >> 3) & 0x70);
}

// pack two fp32 -> half2 (rn)
__device__ __forceinline__ uint32_t pack_h2(float a, float b) {
    uint32_t r;
    asm("{ .reg .f16 lo, hi;\n"
        "cvt.rn.f16.f32 lo, %1;\n"
        "cvt.rn.f16.f32 hi, %2;\n"
        "mov.b32 %0, {lo, hi}; }"
        : "=r"(r) : "f"(a), "f"(b));
    return r;
}

#define MBAR_INIT(addr, cnt) \
    asm volatile("mbarrier.init.shared.b64 [%0], %1;" :: "r"(addr), "r"((uint32_t)(cnt)) : "memory")

#define MBAR_EXPECT_TX(addr, bytes) \
    asm volatile("mbarrier.arrive.expect_tx.shared.b64 _, [%0], %1;" :: "r"(addr), "r"((uint32_t)(bytes)) : "memory")

#define MBAR_ARRIVE(addr) \
    asm volatile("mbarrier.arrive.release.cta.shared.b64 _, [%0];" :: "r"(addr) : "memory")

__device__ __forceinline__ void mbar_wait(uint32_t mbar, uint32_t parity) {
    uint32_t done;
    asm volatile(
        "{ .reg .pred p; mbarrier.try_wait.parity.acquire.cta.shared::cta.b64 p, [%1], %2; selp.b32 %0, 1, 0, p; }"
        : "=r"(done) : "r"(mbar), "r"(parity) : "memory");
    if (!done) {
        asm volatile(
            "{ .reg .pred P1;\n"
            "WL_%=: mbarrier.try_wait.parity.acquire.cta.shared::cta.b64 P1, [%0], %1, 0x989680;\n"
            "@P1 bra.uni WD_%=;\n"
            "bra.uni WL_%=;\n"
            "WD_%=: }"
            :: "r"(mbar), "r"(parity) : "memory");
    }
}

__device__ __forceinline__ void bulk_g2s(uint32_t dst_smem, const void* src_gmem,
                                         uint32_t bytes, uint32_t mbar) {
    asm volatile(
        "cp.async.bulk.shared::cluster.global.mbarrier::complete_tx::bytes [%0], [%1], %2, [%3];"
        :: "r"(dst_smem), "l"(src_gmem), "r"(bytes), "r"(mbar) : "memory");
}

// legacy f16 mma (sm_80 base ISA) -- fallback path only
__device__ __forceinline__ void mma_sync_f16(float* d, const uint32_t* a, const uint32_t* b) {
    asm volatile(
        "mma.sync.aligned.m16n8k16.row.col.f32.f16.f16.f32 "
        "{%0, %1, %2, %3}, {%4, %5, %6, %7}, {%8, %9}, {%0, %1, %2, %3};"
        : "+f"(d[0]), "+f"(d[1]), "+f"(d[2]), "+f"(d[3])
        : "r"(a[0]), "r"(a[1]), "r"(a[2]), "r"(a[3]), "r"(b[0]), "r"(b[1]));
}

#if HAS_TCGEN05
// ============================================================================
// sm_103a-only helpers
// ============================================================================
__device__ __forceinline__ uint32_t elect_one() {
    uint32_t p;
    asm volatile("{ .reg .pred p; elect.sync _|p, 0xFFFFFFFF; selp.b32 %0, 1, 0, p; }" : "=r"(p));
    return p;
}

__device__ __forceinline__ uint64_t make_desc_sw128(uint32_t addr) {
    const uint64_t base = (uint64_t(2) << 61) | (uint64_t(1) << 46) |
                          (uint64_t(64) << 32) | (uint64_t(1) << 16);
    return base | ((uint64_t)(addr >> 4) & 0x3FFF);
}

__device__ __forceinline__ void mma_f16_ss(uint32_t d_tmem, uint64_t a_desc, uint64_t b_desc,
                                           uint32_t idesc, bool acc) {
    uint32_t en = acc ? 1u : 0u;
    asm volatile(
        "{\n\t"
        ".reg .pred p;\n\t"
        "setp.ne.u32 p, %5, 0;\n\t"
        "tcgen05.mma.cta_group::1.kind::f16 [%0], %1, %2, %3, {%4, %4, %4, %4}, p;\n\t"
        "}"
        :: "r"(d_tmem), "l"(a_desc), "l"(b_desc), "r"(idesc), "r"(0u), "r"(en) : "memory");
}

#define TCGEN05_COMMIT(mbar) \
    asm volatile("tcgen05.commit.cta_group::1.mbarrier::arrive::one.shared::cluster.b64 [%0];" \
                 :: "r"(mbar) : "memory")

__device__ __forceinline__ void tcgen05_ld_x32(uint32_t* r, uint32_t tmem_addr) {
    asm volatile(
        "tcgen05.ld.sync.aligned.32x32b.x32.b32 "
        "{%0, %1, %2, %3, %4, %5, %6, %7, "
        " %8, %9, %10, %11, %12, %13, %14, %15, "
        " %16, %17, %18, %19, %20, %21, %22, %23, "
        " %24, %25, %26, %27, %28, %29, %30, %31}, [%32];"
        : "=r"(r[0]), "=r"(r[1]), "=r"(r[2]), "=r"(r[3]),
          "=r"(r[4]), "=r"(r[5]), "=r"(r[6]), "=r"(r[7]),
          "=r"(r[8]), "=r"(r[9]), "=r"(r[10]), "=r"(r[11]),
          "=r"(r[12]), "=r"(r[13]), "=r"(r[14]), "=r"(r[15]),
          "=r"(r[16]), "=r"(r[17]), "=r"(r[18]), "=r"(r[19]),
          "=r"(r[20]), "=r"(r[21]), "=r"(r[22]), "=r"(r[23]),
          "=r"(r[24]), "=r"(r[25]), "=r"(r[26]), "=r"(r[27]),
          "=r"(r[28]), "=r"(r[29]), "=r"(r[30]), "=r"(r[31])
        : "r"(tmem_addr));
}
#endif  // HAS_TCGEN05

// ============================================================================
// Kernel 1 (fused prep): blocks [0, DQ_BLOCKS) dequantize int4 -> fp16 W
// scratch; blocks [DQ_BLOCKS, DQ_BLOCKS+AC_BLOCKS) convert A fp32 -> fp16.
// Both SMEM-free swizzled-STG paths. One launch so the two halves overlap.
// ============================================================================
__global__ void __launch_bounds__(256) prep_kernel(
    const float* __restrict__ inp,
    const int* __restrict__ qweight,
    const float* __restrict__ scales,
    const int* __restrict__ qzeros
) {
    const int t = threadIdx.x;

    if (blockIdx.x < DQ_BLOCKS) {
        // -------- dequant: int4 -> fp16, [N,K] tiled + SW128 swizzled --------
        const int bid = blockIdx.x;
        const int n_tile = bid >> 6;
        const int k_chunk = bid & 63;
        const int k0 = k_chunk * TILE_K;
        const int g = k0 >> 7;            // 64-K chunk never crosses a 128 group

        __shared__ uint32_t sq[TILE_K * 33];
        __shared__ uint32_t sz[32];

        {
            const int k = t >> 2;         // 0..63
            const int nw0 = (t & 3) * 8;  // 0,8,16,24
            const uint32_t* src = (const uint32_t*)qweight +
                                  (size_t)(k0 + k) * NW_TOT + n_tile * 32 + nw0;
            #pragma unroll
            for (int i = 0; i < 8; i++) sq[k * 33 + nw0 + i] = src[i];
            if (t < 32) sz[t] = ((const uint32_t*)qzeros)[(size_t)g * NW_TOT + n_tile * 32 + t];
        }
        __syncthreads();

        char* dst_base = (char*)(g_Ws + (size_t)bid * (256 * TILE_K));
        #pragma unroll
        for (int p = 0; p < 8; p++) {
            const int idx = p * 256 + t;
            const int n_local = idx >> 3;        // 0..255
            const int u = idx & 7;               // 16B unit = 8 K halves
            const int nw = n_local >> 3;
            const int nib = (n_local & 7) * 4;
            const float z = (float)((sz[nw] >> nib) & 15u);
            const float s = __ldg(scales + (size_t)g * N_DIM + n_tile * 256 + n_local);
            float w[8];
            #pragma unroll
            for (int e = 0; e < 8; e++) {
                const float q = (float)((sq[(u * 8 + e) * 33 + nw] >> nib) & 15u);
                w[e] = (q - z) * s;
            }
            *(uint4*)(dst_base + sw128((uint32_t)(n_local * 128 + u * 16))) =
                make_uint4(pack_h2(w[0], w[1]), pack_h2(w[2], w[3]),
                           pack_h2(w[4], w[5]), pack_h2(w[6], w[7]));
        }
    } else {
        // -------- aconv: fp32 -> fp16(rn), [M,K] tiled + SW128 swizzled ------
        const int bid = blockIdx.x - DQ_BLOCKS;
        const int m_tile = bid >> 6;
        const int k_chunk = bid & 63;
        const size_t base_in = (size_t)(m_tile * 128) * K_DIM + k_chunk * TILE_K;
        char* dst_base = (char*)(g_As + (size_t)bid * (128 * TILE_K));

        #pragma unroll
        for (int p = 0; p < 4; p++) {
            const int idx = p * 256 + t;
            const int m_local = idx >> 3;        // 0..127
            const int u = idx & 7;               // 8 K halves per unit
            const float4* src = (const float4*)(inp + base_in + (size_t)m_local * K_DIM + u * 8);
            const float4 f0 = src[0];
            const float4 f1 = src[1];
            *(uint4*)(dst_base + sw128((uint32_t)(m_local * 128 + u * 16))) =
                make_uint4(pack_h2(f0.x, f0.y), pack_h2(f0.z, f0.w),
                           pack_h2(f1.x, f1.y), pack_h2(f1.z, f1.w));
        }
    }
}

// ============================================================================
// Kernel 2: single-CTA 256M x 256N fp16 GEMM, warp-specialized:
//   warp 0 = mma driver (FULL-wait -> 8 mma -> commit EMPTY)
//   warp 1 = fetch warp (EMPTY-gated 3x bulk refill per chunk)
// Two TMEM accumulators (512 cols), 3-stage (64KB) pipeline.
// Fused bias + SiLU + mul epilogue on 8 warps. grid = 688, block = 256.
// ============================================================================
__global__ void __launch_bounds__(256, 1) gemm_kernel(
    const float* __restrict__ bias,
    const float* __restrict__ mul,
    float* __restrict__ out
) {
    extern __shared__ char smem[];
    const uint32_t smem_base = smem_u32(smem);
    const uint32_t data_base = (smem_base + 128 + 1023) & ~1023u;

    const int tid = threadIdx.x;
    const int wid = tid >> 5;
    const int lid = tid & 31;
    const int bid = blockIdx.x;
    const int pm = bid & (M2_TILES - 1);   // m-fast: concurrent CTAs share B via L2
    const int n_tile = bid >> 4;

    const uint32_t FULL0  = smem_base + 8;    // 3 x 8B
    const uint32_t EMPTY0 = smem_base + 32;   // 3 x 8B
    const uint32_t DONE   = smem_base + 56;

#if HAS_TCGEN05
    if (wid == 0) {
        asm volatile("tcgen05.alloc.cta_group::1.sync.aligned.shared::cta.b32 [%0], %1;"
                     :: "r"(smem_base), "r"(512u) : "memory");
        asm volatile("tcgen05.relinquish_alloc_permit.cta_group::1.sync.aligned;");
    }
    if (tid == 0) {
        #pragma unroll
        for (int s = 0; s < STAGES; s++) {
            MBAR_INIT(FULL0 + s * 8, 1);
            MBAR_INIT(EMPTY0 + s * 8, 1);
        }
        MBAR_INIT(DONE, 1);
        asm volatile("fence.proxy.async.shared::cta;" ::: "memory");
    }
    __syncthreads();

    uint32_t tmem_base;
    asm volatile("ld.shared.b32 %0, [%1];" : "=r"(tmem_base) : "r"(smem_base));
    const uint32_t D0 = tmem_base;
    const uint32_t D1 = tmem_base + 256;

    if (wid == 1) {
        // ---------------- fetch warp: all bulk copies, EMPTY-gated ----------
        if (elect_one()) {
            const char* a0_src = reinterpret_cast<const char*>(g_As) +
                                 (size_t)(pm * 2) * K_CHUNKS * A_BLK_BYTES;
            const char* a1_src = a0_src + (size_t)K_CHUNKS * A_BLK_BYTES;
            const char* b_src  = reinterpret_cast<const char*>(g_Ws) +
                                 (size_t)n_tile * K_CHUNKS * B_BLK_BYTES;

            int rs = 0;              // stage cursor for chunk j
            int es = 0, ep = 0;      // EMPTY wait cursor (gates j >= STAGES)
            #pragma unroll 1
            for (int j = 0; j < K_CHUNKS; j++) {
                if (j >= STAGES) {
                    mbar_wait(EMPTY0 + es * 8, ep);
                    if (++es == STAGES) { es = 0; ep ^= 1; }
                }
                const uint32_t fb = FULL0 + rs * 8;
                const uint32_t st = data_base + rs * STAGE_BYTES;
                MBAR_EXPECT_TX(fb, STAGE_BYTES);
                bulk_g2s(st,                   a0_src + (size_t)j * A_BLK_BYTES, A_BLK_BYTES, fb);
                bulk_g2s(st + A_BLK_BYTES,     a1_src + (size_t)j * A_BLK_BYTES, A_BLK_BYTES, fb);
                bulk_g2s(st + 2 * A_BLK_BYTES, b_src  + (size_t)j * B_BLK_BYTES, B_BLK_BYTES, fb);
                if (++rs == STAGES) rs = 0;
            }
        }
        __syncwarp();
    } else if (wid == 0) {
        // ---------------- mma warp: pure tensor issue ------------------------
        if (elect_one()) {
            int fs = 0, fp = 0;
            #pragma unroll 1
            for (int it = 0; it < K_CHUNKS; it++) {
                mbar_wait(FULL0 + fs * 8, fp);
                const uint32_t st = data_base + fs * STAGE_BYTES;
                const uint64_t a0d = make_desc_sw128(st);
                const uint64_t a1d = make_desc_sw128(st + A_BLK_BYTES);
                const uint64_t bd  = make_desc_sw128(st + 2 * A_BLK_BYTES);
                #pragma unroll
                for (int ks = 0; ks < 4; ks++) {   // 4 x K=16 fp16 steps = 64 K
                    mma_f16_ss(D0, a0d + ks * 2, bd + ks * 2, MMA_IDESC_F16, (it | ks) != 0);
                    mma_f16_ss(D1, a1d + ks * 2, bd + ks * 2, MMA_IDESC_F16, (it | ks) != 0);
                }
                TCGEN05_COMMIT(EMPTY0 + fs * 8);
                if (++fs == STAGES) { fs = 0; fp ^= 1; }
            }
            TCGEN05_COMMIT(DONE);
        }
        __syncwarp();
    }

    // ---------------- epilogue: 8 warps; warps 0-3 -> D0 rows, 4-7 -> D1 rows ----
    mbar_wait(DONE, 0);
    asm volatile("tcgen05.fence::after_thread_sync;" ::: "memory");

    const int mhalf = wid >> 2;
    const uint32_t dbase = tmem_base + mhalf * 256;
    const int m = pm * 256 + mhalf * 128 + (wid & 3) * 32 + lid;
    const int n_base = n_tile * 256;
    const float4* mul4 = reinterpret_cast<const float4*>(mul + (size_t)m * N_DIM + n_base);
    float4* out4 = reinterpret_cast<float4*>(out + (size_t)m * N_DIM + n_base);

    #pragma unroll 1
    for (int cc = 0; cc < 8; cc++) {
        uint32_t d[32];
        tcgen05_ld_x32(d, dbase + cc * 32);
        asm volatile("tcgen05.wait::ld.sync.aligned;" ::: "memory");
        #pragma unroll
        for (int v = 0; v < 8; v++) {
            const float4 mv = mul4[cc * 8 + v];
            const float mvf[4] = {mv.x, mv.y, mv.z, mv.w};
            float o[4];
            #pragma unroll
            for (int e = 0; e < 4; e++) {
                const int j = v * 4 + e;
                const float x = __uint_as_float(d[j]) + __ldg(bias + n_base + cc * 32 + j);
                const float sg = 1.0f / (1.0f + __expf(-x));
                o[e] = x * sg * mvf[e];
            }
            out4[cc * 8 + v] = make_float4(o[0], o[1], o[2], o[3]);
        }
    }

    __syncthreads();
    if (wid == 0) {
        asm volatile("tcgen05.dealloc.cta_group::1.sync.aligned.b32 %0, %1;"
                     :: "r"(tmem_base), "r"(512u));
    }

#else
    // ------------------------------------------------------------- fallback path
    // Base compute_103 pass (never selected on sm_103a hardware; must compile).
    // m16n8k16 f16 mma; flat 128-iteration pipeline: j = mh*64 + it.
    if (tid == 0) {
        #pragma unroll
        for (int s = 0; s < FB_STAGES; s++) {
            MBAR_INIT(FULL0 + s * 8, 1);
            MBAR_INIT(EMPTY0 + s * 8, 8);
        }
        asm volatile("fence.proxy.async.shared::cta;" ::: "memory");
    }
    __syncthreads();

    const uint32_t data_off = data_base - smem_base;
    const int m0w = (wid >> 2) * 64;
    const int n0w = (wid & 3) * 64;
    const int ar = lid >> 2;
    const int ac = lid & 3;

    const char* b_src = reinterpret_cast<const char*>(g_Ws) +
                        (size_t)n_tile * K_CHUNKS * B_BLK_BYTES;

    if (tid == 0) {
        #pragma unroll
        for (int j = 0; j < FB_STAGES - 1; j++) {
            const char* a_src = reinterpret_cast<const char*>(g_As) +
                                (size_t)(pm * 2 + (j >> 6)) * K_CHUNKS * A_BLK_BYTES;
            const uint32_t fb = FULL0 + (j & 3) * 8;
            MBAR_EXPECT_TX(fb, FB_STAGE_BYTES);
            bulk_g2s(data_base + (j & 3) * FB_STAGE_BYTES,
                     a_src + (size_t)(j & 63) * A_BLK_BYTES, A_BLK_BYTES, fb);
            bulk_g2s(data_base + (j & 3) * FB_STAGE_BYTES + A_BLK_BYTES,
                     b_src + (size_t)(j & 63) * B_BLK_BYTES, B_BLK_BYTES, fb);
        }
    }

    #pragma unroll 1
    for (int mh = 0; mh < 2; mh++) {
        float acc[4][8][4];
        #pragma unroll
        for (int mi = 0; mi < 4; mi++)
            #pragma unroll
            for (int ni = 0; ni < 8; ni++)
                #pragma unroll
                for (int e = 0; e < 4; e++) acc[mi][ni][e] = 0.0f;

        #pragma unroll 1
        for (int it = 0; it < K_CHUNKS; it++) {
            const int gj = mh * K_CHUNKS + it;
            const int s = gj & 3;
            mbar_wait(FULL0 + s * 8, (gj >> 2) & 1);

            const uint32_t a_base = data_off + s * FB_STAGE_BYTES;
            const uint32_t b_base = a_base + A_BLK_BYTES;

            #pragma unroll
            for (int ks = 0; ks < 4; ks++) {
                uint32_t afr[4][4];
                #pragma unroll
                for (int mi = 0; mi < 4; mi++) {
                    const int r0 = m0w + mi * 16 + ar;
                    const int c = ks * 16 + ac * 2;
                    afr[mi][0] = *(const uint32_t*)(smem + a_base + sw128(r0 * 128 + c * 2));
                    afr[mi][1] = *(const uint32_t*)(smem + a_base + sw128((r0 + 8) * 128 + c * 2));
                    afr[mi][2] = *(const uint32_t*)(smem + a_base + sw128(r0 * 128 + (c + 8) * 2));
                    afr[mi][3] = *(const uint32_t*)(smem + a_base + sw128((r0 + 8) * 128 + (c + 8) * 2));
                }
                uint32_t bfr[8][2];
                #pragma unroll
                for (int ni = 0; ni < 8; ni++) {
                    const int bn = n0w + ni * 8 + ar;
                    const int bk = ks * 16 + ac * 2;
                    bfr[ni][0] = *(const uint32_t*)(smem + b_base + sw128(bn * 128 + bk * 2));
                    bfr[ni][1] = *(const uint32_t*)(smem + b_base + sw128(bn * 128 + (bk + 8) * 2));
                }
                #pragma unroll
                for (int mi = 0; mi < 4; mi++)
                    #pragma unroll
                    for (int ni = 0; ni < 8; ni++)
                        mma_sync_f16(acc[mi][ni], afr[mi], bfr[ni]);
            }

            if (lid == 0) MBAR_ARRIVE(EMPTY0 + s * 8);

            const int j = gj + FB_STAGES - 1;
            if (j < 2 * K_CHUNKS && tid == 0) {
                const int s2 = j & 3;
                if (j >= FB_STAGES) mbar_wait(EMPTY0 + s2 * 8, ((j - FB_STAGES) >> 2) & 1);
                const char* a_src = reinterpret_cast<const char*>(g_As) +
                                    (size_t)(pm * 2 + (j >> 6)) * K_CHUNKS * A_BLK_BYTES;
                const uint32_t fb = FULL0 + s2 * 8;
                MBAR_EXPECT_TX(fb, FB_STAGE_BYTES);
                bulk_g2s(data_base + s2 * FB_STAGE_BYTES,
                         a_src + (size_t)(j & 63) * A_BLK_BYTES, A_BLK_BYTES, fb);
                bulk_g2s(data_base + s2 * FB_STAGE_BYTES + A_BLK_BYTES,
                         b_src + (size_t)(j & 63) * B_BLK_BYTES, B_BLK_BYTES, fb);
            }
        }

        const int gm0 = pm * 256 + mh * 128 + m0w;
        const int gn0 = n_tile * 256 + n0w;
        #pragma unroll
        for (int mi = 0; mi < 4; mi++) {
            #pragma unroll
            for (int hrow = 0; hrow < 2; hrow++) {
                const int m = gm0 + mi * 16 + hrow * 8 + (lid >> 2);
                #pragma unroll
                for (int ni = 0; ni < 8; ni++) {
                    const int n = gn0 + ni * 8 + (lid & 3) * 2;
                    const float2 mv = *reinterpret_cast<const float2*>(mul + (size_t)m * N_DIM + n);
                    float o[2];
                    #pragma unroll
                    for (int e = 0; e < 2; e++) {
                        const float x = acc[mi][ni][hrow * 2 + e] + __ldg(bias + n + e);
                        const float sg = 1.0f / (1.0f + __expf(-x));
                        o[e] = x * sg * ((e == 0) ? mv.x : mv.y);
                    }
                    *reinterpret_cast<float2*>(out + (size_t)m * N_DIM + n) = make_float2(o[0], o[1]);
                }
            }
        }
    }
#endif
}

// ============================================================================
// Launch
// ============================================================================
extern "C" void kernel_launch(void* const* d_in, const int* in_sizes, int n_in,
                              void* d_out, int out_size) {
    const float* inp     = (const float*)d_in[0];
    const int*   qweight = (const int*)d_in[1];
    const float* scales  = (const float*)d_in[2];
    const int*   qzeros  = (const int*)d_in[3];
    const float* bias    = (const float*)d_in[4];
    const float* mul     = (const float*)d_in[5];
    float* out = (float*)d_out;

    cudaFuncSetAttribute(gemm_kernel, cudaFuncAttributeMaxDynamicSharedMemorySize,
                         GEMM_SMEM_BYTES);

    prep_kernel<<<DQ_BLOCKS + AC_BLOCKS, 256>>>(inp, qweight, scales, qzeros);
    gemm_kernel<<<M2_TILES * N_TILES, 256, GEMM_SMEM_BYTES>>>(bias, mul, out);
}

// round 8
// speedup vs baseline: 3.0434x; 1.0147x over previous
#include <cuda_runtime.h>
#include <cuda_fp16.h>
#include <cstdint>
#include <cstddef>

// ============================================================================
// Arch feature detection: tcgen05 needs the 'a' target (sm_103a).
// The harness also builds a base compute_103 PTX pass -> guarded fallback.
// ============================================================================
#if defined(__CUDA_ARCH_FEAT_SM103_ALL) || defined(__CUDA_ARCH_FEAT_SM100_ALL) || defined(__CUDA_ARCH_FEAT_SM101_ALL)
#define HAS_TCGEN05 1
#else
#define HAS_TCGEN05 0
#endif

// ============================================================================
// Problem constants
// ============================================================================
#define M_DIM 4096
#define K_DIM 4096
#define N_DIM 11008
#define NW_TOT (N_DIM / 8)
#define GROUP 128

#define TILE_K 32                     // 32 fp16 = 64B = one SW64 row
#define K_CHUNKS (K_DIM / TILE_K)     // 128
#define M_TILES 32                    // 128-row A scratch blocks
#define N_TILES 43                    // 256-row W scratch blocks
#define M2_TILES 16                   // 256-row CTA tiles

#define A_BLK_BYTES (128 * TILE_K * 2)    // 8192
#define B_BLK_BYTES (256 * TILE_K * 2)    // 16384

// GEMM pipeline: stage = A0(8K) + A1(8K) + B(16K) = 32KB, 6 stages
#define STAGES 6
#define STAGE_BYTES (2 * A_BLK_BYTES + B_BLK_BYTES)   // 32768
#define GEMM_SMEM_BYTES (2048 + STAGES * STAGE_BYTES) // 198656

// fallback pipeline (base compute_103 pass only): stage = A half + B = 24KB
#define FB_STAGES 4
#define FB_STAGE_BYTES (A_BLK_BYTES + B_BLK_BYTES)    // 24576

// fused prep kernel block ranges
#define DQ_BLOCKS (N_TILES * K_CHUNKS)     // 5504
#define AC_BLOCKS (M_TILES * K_CHUNKS)     // 4096

// idesc kind::f16, fp16 a/b, fp32 d (cg1, M=128, N=256):
// dfmt=F32(1)<<4, atype=FP16(0)<<7, btype=FP16(0)<<10, N/8=32 @[17:23), M/16=8 @[24:29)
#define MMA_IDESC_F16 ((1u << 4) | (32u << 17) | (8u << 24))

// Scratch: pre-tiled, pre-SW64-swizzled fp16 operands (64B rows, K=32 per block).
__device__ __align__(1024) uint16_t g_As[(size_t)M_TILES * K_CHUNKS * (128 * TILE_K)];
__device__ __align__(1024) uint16_t g_Ws[(size_t)N_TILES * K_CHUNKS * (256 * TILE_K)];

// ============================================================================
// Base-ISA helpers
// ============================================================================
__device__ __forceinline__ uint32_t smem_u32(const void* p) {
    uint32_t a;
    asm("{ .reg .u64 t; cvta.to.shared.u64 t, %1; cvt.u32.u64 %0, t; }" : "=r"(a) : "l"(p));
    return a;
}

// SW64 swizzle: bits [5:4] ^= bits [9:8]>>... (byte_off >> 3) & 0x30
__device__ __forceinline__ uint32_t sw64(uint32_t byte_off) {
    return byte_off ^ ((byte_off >> 3) & 0x30);
}

// pack two fp32 -> half2 (rn)
__device__ __forceinline__ uint32_t pack_h2(float a, float b) {
    uint32_t r;
    asm("{ .reg .f16 lo, hi;\n"
        "cvt.rn.f16.f32 lo, %1;\n"
        "cvt.rn.f16.f32 hi, %2;\n"
        "mov.b32 %0, {lo, hi}; }"
        : "=r"(r) : "f"(a), "f"(b));
    return r;
}

#define MBAR_INIT(addr, cnt) \
    asm volatile("mbarrier.init.shared.b64 [%0], %1;" :: "r"(addr), "r"((uint32_t)(cnt)) : "memory")

#define MBAR_EXPECT_TX(addr, bytes) \
    asm volatile("mbarrier.arrive.expect_tx.shared.b64 _, [%0], %1;" :: "r"(addr), "r"((uint32_t)(bytes)) : "memory")

#define MBAR_ARRIVE(addr) \
    asm volatile("mbarrier.arrive.release.cta.shared.b64 _, [%0];" :: "r"(addr) : "memory")

__device__ __forceinline__ void mbar_wait(uint32_t mbar, uint32_t parity) {
    uint32_t done;
    asm volatile(
        "{ .reg .pred p; mbarrier.try_wait.parity.acquire.cta.shared::cta.b64 p, [%1], %2; selp.b32 %0, 1, 0, p; }"
        : "=r"(done) : "r"(mbar), "r"(parity) : "memory");
    if (!done) {
        asm volatile(
            "{ .reg .pred P1;\n"
            "WL_%=: mbarrier.try_wait.parity.acquire.cta.shared::cta.b64 P1, [%0], %1, 0x989680;\n"
            "@P1 bra.uni WD_%=;\n"
            "bra.uni WL_%=;\n"
            "WD_%=: }"
            :: "r"(mbar), "r"(parity) : "memory");
    }
}

__device__ __forceinline__ void bulk_g2s(uint32_t dst_smem, const void* src_gmem,
                                         uint32_t bytes, uint32_t mbar) {
    asm volatile(
        "cp.async.bulk.shared::cluster.global.mbarrier::complete_tx::bytes [%0], [%1], %2, [%3];"
        :: "r"(dst_smem), "l"(src_gmem), "r"(bytes), "r"(mbar) : "memory");
}

// legacy f16 mma (sm_80 base ISA) -- fallback path only
__device__ __forceinline__ void mma_sync_f16(float* d, const uint32_t* a, const uint32_t* b) {
    asm volatile(
        "mma.sync.aligned.m16n8k16.row.col.f32.f16.f16.f32 "
        "{%0, %1, %2, %3}, {%4, %5, %6, %7}, {%8, %9}, {%0, %1, %2, %3};"
        : "+f"(d[0]), "+f"(d[1]), "+f"(d[2]), "+f"(d[3])
        : "r"(a[0]), "r"(a[1]), "r"(a[2]), "r"(a[3]), "r"(b[0]), "r"(b[1]));
}

#if HAS_TCGEN05
// ============================================================================
// sm_103a-only helpers
// ============================================================================
__device__ __forceinline__ uint32_t elect_one() {
    uint32_t p;
    asm volatile("{ .reg .pred p; elect.sync _|p, 0xFFFFFFFF; selp.b32 %0, 1, 0, p; }" : "=r"(p));
    return p;
}

// SW64 K-major descriptor: layout=4, version=1 (Blackwell), SBO=32 (8 rows x 64B
// = 512B = 32 x 16B), LBO=1 (16B inner stride)
__device__ __forceinline__ uint64_t make_desc_sw64(uint32_t addr) {
    const uint64_t base = (uint64_t(4) << 61) | (uint64_t(1) << 46) |
                          (uint64_t(32) << 32) | (uint64_t(1) << 16);
    return base | ((uint64_t)(addr >> 4) & 0x3FFF);
}

__device__ __forceinline__ void mma_f16_ss(uint32_t d_tmem, uint64_t a_desc, uint64_t b_desc,
                                           uint32_t idesc, bool acc) {
    uint32_t en = acc ? 1u : 0u;
    asm volatile(
        "{\n\t"
        ".reg .pred p;\n\t"
        "setp.ne.u32 p, %5, 0;\n\t"
        "tcgen05.mma.cta_group::1.kind::f16 [%0], %1, %2, %3, {%4, %4, %4, %4}, p;\n\t"
        "}"
        :: "r"(d_tmem), "l"(a_desc), "l"(b_desc), "r"(idesc), "r"(0u), "r"(en) : "memory");
}

#define TCGEN05_COMMIT(mbar) \
    asm volatile("tcgen05.commit.cta_group::1.mbarrier::arrive::one.shared::cluster.b64 [%0];" \
                 :: "r"(mbar) : "memory")

__device__ __forceinline__ void tcgen05_ld_x32(uint32_t* r, uint32_t tmem_addr) {
    asm volatile(
        "tcgen05.ld.sync.aligned.32x32b.x32.b32 "
        "{%0, %1, %2, %3, %4, %5, %6, %7, "
        " %8, %9, %10, %11, %12, %13, %14, %15, "
        " %16, %17, %18, %19, %20, %21, %22, %23, "
        " %24, %25, %26, %27, %28, %29, %30, %31}, [%32];"
        : "=r"(r[0]), "=r"(r[1]), "=r"(r[2]), "=r"(r[3]),
          "=r"(r[4]), "=r"(r[5]), "=r"(r[6]), "=r"(r[7]),
          "=r"(r[8]), "=r"(r[9]), "=r"(r[10]), "=r"(r[11]),
          "=r"(r[12]), "=r"(r[13]), "=r"(r[14]), "=r"(r[15]),
          "=r"(r[16]), "=r"(r[17]), "=r"(r[18]), "=r"(r[19]),
          "=r"(r[20]), "=r"(r[21]), "=r"(r[22]), "=r"(r[23]),
          "=r"(r[24]), "=r"(r[25]), "=r"(r[26]), "=r"(r[27]),
          "=r"(r[28]), "=r"(r[29]), "=r"(r[30]), "=r"(r[31])
        : "r"(tmem_addr));
}
#endif  // HAS_TCGEN05

// ============================================================================
// Kernel 1 (fused prep): blocks [0, DQ_BLOCKS) dequantize int4 -> fp16 W
// scratch; blocks [DQ_BLOCKS, ..) convert A fp32 -> fp16. SMEM-free swizzled
// STG paths (SW64 permutes 16B units; aligned uint4 stores land correctly).
// ============================================================================
__global__ void __launch_bounds__(256) prep_kernel(
    const float* __restrict__ inp,
    const int* __restrict__ qweight,
    const float* __restrict__ scales,
    const int* __restrict__ qzeros
) {
    const int t = threadIdx.x;

    if (blockIdx.x < DQ_BLOCKS) {
        // -------- dequant: int4 -> fp16, [N,K=32] tiled + SW64 swizzled -------
        const int bid = blockIdx.x;
        const int n_tile = bid >> 7;
        const int k_chunk = bid & 127;
        const int k0 = k_chunk * TILE_K;
        const int g = k0 >> 7;            // 32-K chunk never crosses a 128 group

        __shared__ uint32_t sq[TILE_K * 33];   // 32 k-rows x 32 n-words
        __shared__ uint32_t sz[32];

        {
            const int k = t >> 3;         // 0..31
            const int nw0 = (t & 7) * 4;  // 0,4,...,28
            const uint32_t* src = (const uint32_t*)qweight +
                                  (size_t)(k0 + k) * NW_TOT + n_tile * 32 + nw0;
            #pragma unroll
            for (int i = 0; i < 4; i++) sq[k * 33 + nw0 + i] = src[i];
            if (t < 32) sz[t] = ((const uint32_t*)qzeros)[(size_t)g * NW_TOT + n_tile * 32 + t];
        }
        __syncthreads();

        char* dst_base = (char*)(g_Ws + (size_t)bid * (256 * TILE_K));
        #pragma unroll
        for (int p = 0; p < 4; p++) {
            const int idx = p * 256 + t;
            const int n_local = idx >> 2;        // 0..255
            const int u = idx & 3;               // 16B unit = 8 K halves
            const int nw = n_local >> 3;
            const int nib = (n_local & 7) * 4;
            const float z = (float)((sz[nw] >> nib) & 15u);
            const float s = __ldg(scales + (size_t)g * N_DIM + n_tile * 256 + n_local);
            float w[8];
            #pragma unroll
            for (int e = 0; e < 8; e++) {
                const float q = (float)((sq[(u * 8 + e) * 33 + nw] >> nib) & 15u);
                w[e] = (q - z) * s;
            }
            *(uint4*)(dst_base + sw64((uint32_t)(n_local * 64 + u * 16))) =
                make_uint4(pack_h2(w[0], w[1]), pack_h2(w[2], w[3]),
                           pack_h2(w[4], w[5]), pack_h2(w[6], w[7]));
        }
    } else {
        // -------- aconv: fp32 -> fp16(rn), [M,K=32] tiled + SW64 swizzled -----
        const int bid = blockIdx.x - DQ_BLOCKS;
        const int m_tile = bid >> 7;
        const int k_chunk = bid & 127;
        const size_t base_in = (size_t)(m_tile * 128) * K_DIM + k_chunk * TILE_K;
        char* dst_base = (char*)(g_As + (size_t)bid * (128 * TILE_K));

        #pragma unroll
        for (int p = 0; p < 2; p++) {
            const int idx = p * 256 + t;
            const int m_local = idx >> 2;        // 0..127
            const int u = idx & 3;               // 8 K halves per unit
            const float4* src = (const float4*)(inp + base_in + (size_t)m_local * K_DIM + u * 8);
            const float4 f0 = src[0];
            const float4 f1 = src[1];
            *(uint4*)(dst_base + sw64((uint32_t)(m_local * 64 + u * 16))) =
                make_uint4(pack_h2(f0.x, f0.y), pack_h2(f0.z, f0.w),
                           pack_h2(f1.x, f1.y), pack_h2(f1.z, f1.w));
        }
    }
}

// ============================================================================
// Kernel 2: single-CTA 256M x 256N fp16 GEMM, warp-specialized:
//   warp 0 = mma driver (FULL-wait -> 4 mma -> commit EMPTY), 128 x 32-K chunks
//   warp 1 = fetch warp (EMPTY-gated 3x bulk refill per chunk)
// Two TMEM accumulators (512 cols), 6-stage (32KB) pipeline.
// Fused bias + SiLU + mul epilogue on 8 warps. grid = 688, block = 256.
// ============================================================================
__global__ void __launch_bounds__(256, 1) gemm_kernel(
    const float* __restrict__ bias,
    const float* __restrict__ mul,
    float* __restrict__ out
) {
    extern __shared__ char smem[];
    const uint32_t smem_base = smem_u32(smem);
    const uint32_t data_base = (smem_base + 128 + 1023) & ~1023u;

    const int tid = threadIdx.x;
    const int wid = tid >> 5;
    const int lid = tid & 31;
    const int bid = blockIdx.x;
    const int pm = bid & (M2_TILES - 1);   // m-fast: concurrent CTAs share B via L2
    const int n_tile = bid >> 4;

    const uint32_t FULL0  = smem_base + 8;    // 6 x 8B
    const uint32_t EMPTY0 = smem_base + 56;   // 6 x 8B
    const uint32_t DONE   = smem_base + 104;

#if HAS_TCGEN05
    if (wid == 0) {
        asm volatile("tcgen05.alloc.cta_group::1.sync.aligned.shared::cta.b32 [%0], %1;"
                     :: "r"(smem_base), "r"(512u) : "memory");
        asm volatile("tcgen05.relinquish_alloc_permit.cta_group::1.sync.aligned;");
    }
    if (tid == 0) {
        #pragma unroll
        for (int s = 0; s < STAGES; s++) {
            MBAR_INIT(FULL0 + s * 8, 1);
            MBAR_INIT(EMPTY0 + s * 8, 1);
        }
        MBAR_INIT(DONE, 1);
        asm volatile("fence.proxy.async.shared::cta;" ::: "memory");
    }
    __syncthreads();

    uint32_t tmem_base;
    asm volatile("ld.shared.b32 %0, [%1];" : "=r"(tmem_base) : "r"(smem_base));
    const uint32_t D0 = tmem_base;
    const uint32_t D1 = tmem_base + 256;

    if (wid == 1) {
        // ---------------- fetch warp: all bulk copies, EMPTY-gated ----------
        if (elect_one()) {
            const char* a0_src = reinterpret_cast<const char*>(g_As) +
                                 (size_t)(pm * 2) * K_CHUNKS * A_BLK_BYTES;
            const char* a1_src = a0_src + (size_t)K_CHUNKS * A_BLK_BYTES;
            const char* b_src  = reinterpret_cast<const char*>(g_Ws) +
                                 (size_t)n_tile * K_CHUNKS * B_BLK_BYTES;

            int rs = 0;              // stage cursor for chunk j
            int es = 0, ep = 0;      // EMPTY wait cursor (gates j >= STAGES)
            #pragma unroll 1
            for (int j = 0; j < K_CHUNKS; j++) {
                if (j >= STAGES) {
                    mbar_wait(EMPTY0 + es * 8, ep);
                    if (++es == STAGES) { es = 0; ep ^= 1; }
                }
                const uint32_t fb = FULL0 + rs * 8;
                const uint32_t st = data_base + rs * STAGE_BYTES;
                MBAR_EXPECT_TX(fb, STAGE_BYTES);
                bulk_g2s(st,                   a0_src + (size_t)j * A_BLK_BYTES, A_BLK_BYTES, fb);
                bulk_g2s(st + A_BLK_BYTES,     a1_src + (size_t)j * A_BLK_BYTES, A_BLK_BYTES, fb);
                bulk_g2s(st + 2 * A_BLK_BYTES, b_src  + (size_t)j * B_BLK_BYTES, B_BLK_BYTES, fb);
                if (++rs == STAGES) rs = 0;
            }
        }
        __syncwarp();
    } else if (wid == 0) {
        // ---------------- mma warp: pure tensor issue ------------------------
        if (elect_one()) {
            int fs = 0, fp = 0;
            #pragma unroll 1
            for (int it = 0; it < K_CHUNKS; it++) {
                mbar_wait(FULL0 + fs * 8, fp);
                const uint32_t st = data_base + fs * STAGE_BYTES;
                const uint64_t a0d = make_desc_sw64(st);
                const uint64_t a1d = make_desc_sw64(st + A_BLK_BYTES);
                const uint64_t bd  = make_desc_sw64(st + 2 * A_BLK_BYTES);
                #pragma unroll
                for (int ks = 0; ks < 2; ks++) {   // 2 x K=16 fp16 steps = 32 K
                    mma_f16_ss(D0, a0d + ks * 2, bd + ks * 2, MMA_IDESC_F16, (it | ks) != 0);
                    mma_f16_ss(D1, a1d + ks * 2, bd + ks * 2, MMA_IDESC_F16, (it | ks) != 0);
                }
                TCGEN05_COMMIT(EMPTY0 + fs * 8);
                if (++fs == STAGES) { fs = 0; fp ^= 1; }
            }
            TCGEN05_COMMIT(DONE);
        }
        __syncwarp();
    }

    // ---------------- epilogue: 8 warps; warps 0-3 -> D0 rows, 4-7 -> D1 rows ----
    mbar_wait(DONE, 0);
    asm volatile("tcgen05.fence::after_thread_sync;" ::: "memory");

    const int mhalf = wid >> 2;
    const uint32_t dbase = tmem_base + mhalf * 256;
    const int m = pm * 256 + mhalf * 128 + (wid & 3) * 32 + lid;
    const int n_base = n_tile * 256;
    const float4* mul4 = reinterpret_cast<const float4*>(mul + (size_t)m * N_DIM + n_base);
    float4* out4 = reinterpret_cast<float4*>(out + (size_t)m * N_DIM + n_base);

    #pragma unroll 1
    for (int cc = 0; cc < 8; cc++) {
        uint32_t d[32];
        tcgen05_ld_x32(d, dbase + cc * 32);
        asm volatile("tcgen05.wait::ld.sync.aligned;" ::: "memory");
        #pragma unroll
        for (int v = 0; v < 8; v++) {
            const float4 mv = mul4[cc * 8 + v];
            const float mvf[4] = {mv.x, mv.y, mv.z, mv.w};
            float o[4];
            #pragma unroll
            for (int e = 0; e < 4; e++) {
                const int j = v * 4 + e;
                const float x = __uint_as_float(d[j]) + __ldg(bias + n_base + cc * 32 + j);
                const float sg = 1.0f / (1.0f + __expf(-x));
                o[e] = x * sg * mvf[e];
            }
            out4[cc * 8 + v] = make_float4(o[0], o[1], o[2], o[3]);
        }
    }

    __syncthreads();
    if (wid == 0) {
        asm volatile("tcgen05.dealloc.cta_group::1.sync.aligned.b32 %0, %1;"
                     :: "r"(tmem_base), "r"(512u));
    }

#else
    // ------------------------------------------------------------- fallback path
    // Base compute_103 pass (never selected on sm_103a hardware; must compile).
    // m16n8k16 f16 mma; flat 256-iteration pipeline: j = mh*128 + it; SW64 rows.
    if (tid == 0) {
        #pragma unroll
        for (int s = 0; s < FB_STAGES; s++) {
            MBAR_INIT(FULL0 + s * 8, 1);
            MBAR_INIT(EMPTY0 + s * 8, 8);
        }
        asm volatile("fence.proxy.async.shared::cta;" ::: "memory");
    }
    __syncthreads();

    const uint32_t data_off = data_base - smem_base;
    const int m0w = (wid >> 2) * 64;
    const int n0w = (wid & 3) * 64;
    const int ar = lid >> 2;
    const int ac = lid & 3;

    const char* b_src = reinterpret_cast<const char*>(g_Ws) +
                        (size_t)n_tile * K_CHUNKS * B_BLK_BYTES;

    if (tid == 0) {
        #pragma unroll
        for (int j = 0; j < FB_STAGES - 1; j++) {
            const char* a_src = reinterpret_cast<const char*>(g_As) +
                                (size_t)(pm * 2 + (j >> 7)) * K_CHUNKS * A_BLK_BYTES;
            const uint32_t fb = FULL0 + (j & 3) * 8;
            MBAR_EXPECT_TX(fb, FB_STAGE_BYTES);
            bulk_g2s(data_base + (j & 3) * FB_STAGE_BYTES,
                     a_src + (size_t)(j & 127) * A_BLK_BYTES, A_BLK_BYTES, fb);
            bulk_g2s(data_base + (j & 3) * FB_STAGE_BYTES + A_BLK_BYTES,
                     b_src + (size_t)(j & 127) * B_BLK_BYTES, B_BLK_BYTES, fb);
        }
    }

    #pragma unroll 1
    for (int mh = 0; mh < 2; mh++) {
        float acc[4][8][4];
        #pragma unroll
        for (int mi = 0; mi < 4; mi++)
            #pragma unroll
            for (int ni = 0; ni < 8; ni++)
                #pragma unroll
                for (int e = 0; e < 4; e++) acc[mi][ni][e] = 0.0f;

        #pragma unroll 1
        for (int it = 0; it < K_CHUNKS; it++) {
            const int gj = mh * K_CHUNKS + it;
            const int s = gj & 3;
            mbar_wait(FULL0 + s * 8, (gj >> 2) & 1);

            const uint32_t a_base = data_off + s * FB_STAGE_BYTES;
            const uint32_t b_base = a_base + A_BLK_BYTES;

            #pragma unroll
            for (int ks = 0; ks < 2; ks++) {       // 2 x K=16 per 32-K chunk
                uint32_t afr[4][4];
                #pragma unroll
                for (int mi = 0; mi < 4; mi++) {
                    const int r0 = m0w + mi * 16 + ar;
                    const int c = ks * 16 + ac * 2;            // fp16 col
                    afr[mi][0] = *(const uint32_t*)(smem + a_base + sw64(r0 * 64 + c * 2));
                    afr[mi][1] = *(const uint32_t*)(smem + a_base + sw64((r0 + 8) * 64 + c * 2));
                    afr[mi][2] = *(const uint32_t*)(smem + a_base + sw64(r0 * 64 + (c + 8) * 2));
                    afr[mi][3] = *(const uint32_t*)(smem + a_base + sw64((r0 + 8) * 64 + (c + 8) * 2));
                }
                uint32_t bfr[8][2];
                #pragma unroll
                for (int ni = 0; ni < 8; ni++) {
                    const int bn = n0w + ni * 8 + ar;
                    const int bk = ks * 16 + ac * 2;
                    bfr[ni][0] = *(const uint32_t*)(smem + b_base + sw64(bn * 64 + bk * 2));
                    bfr[ni][1] = *(const uint32_t*)(smem + b_base + sw64(bn * 64 + (bk + 8) * 2));
                }
                #pragma unroll
                for (int mi = 0; mi < 4; mi++)
                    #pragma unroll
                    for (int ni = 0; ni < 8; ni++)
                        mma_sync_f16(acc[mi][ni], afr[mi], bfr[ni]);
            }

            if (lid == 0) MBAR_ARRIVE(EMPTY0 + s * 8);

            const int j = gj + FB_STAGES - 1;
            if (j < 2 * K_CHUNKS && tid == 0) {
                const int s2 = j & 3;
                if (j >= FB_STAGES) mbar_wait(EMPTY0 + s2 * 8, ((j - FB_STAGES) >> 2) & 1);
                const char* a_src = reinterpret_cast<const char*>(g_As) +
                                    (size_t)(pm * 2 + (j >> 7)) * K_CHUNKS * A_BLK_BYTES;
                const uint32_t fb = FULL0 + s2 * 8;
                MBAR_EXPECT_TX(fb, FB_STAGE_BYTES);
                bulk_g2s(data_base + s2 * FB_STAGE_BYTES,
                         a_src + (size_t)(j & 127) * A_BLK_BYTES, A_BLK_BYTES, fb);
                bulk_g2s(data_base + s2 * FB_STAGE_BYTES + A_BLK_BYTES,
                         b_src + (size_t)(j & 127) * B_BLK_BYTES, B_BLK_BYTES, fb);
            }
        }

        const int gm0 = pm * 256 + mh * 128 + m0w;
        const int gn0 = n_tile * 256 + n0w;
        #pragma unroll
        for (int mi = 0; mi < 4; mi++) {
            #pragma unroll
            for (int hrow = 0; hrow < 2; hrow++) {
                const int m = gm0 + mi * 16 + hrow * 8 + (lid >> 2);
                #pragma unroll
                for (int ni = 0; ni < 8; ni++) {
                    const int n = gn0 + ni * 8 + (lid & 3) * 2;
                    const float2 mv = *reinterpret_cast<const float2*>(mul + (size_t)m * N_DIM + n);
                    float o[2];
                    #pragma unroll
                    for (int e = 0; e < 2; e++) {
                        const float x = acc[mi][ni][hrow * 2 + e] + __ldg(bias + n + e);
                        const float sg = 1.0f / (1.0f + __expf(-x));
                        o[e] = x * sg * ((e == 0) ? mv.x : mv.y);
                    }
                    *reinterpret_cast<float2*>(out + (size_t)m * N_DIM + n) = make_float2(o[0], o[1]);
                }
            }
        }
    }
#endif
}

// ============================================================================
// Launch
// ============================================================================
extern "C" void kernel_launch(void* const* d_in, const int* in_sizes, int n_in,
                              void* d_out, int out_size) {
    const float* inp     = (const float*)d_in[0];
    const int*   qweight = (const int*)d_in[1];
    const float* scales  = (const float*)d_in[2];
    const int*   qzeros  = (const int*)d_in[3];
    const float* bias    = (const float*)d_in[4];
    const float* mul     = (const float*)d_in[5];
    float* out = (float*)d_out;

    cudaFuncSetAttribute(gemm_kernel, cudaFuncAttributeMaxDynamicSharedMemorySize,
                         GEMM_SMEM_BYTES);

    prep_kernel<<<DQ_BLOCKS + AC_BLOCKS, 256>>>(inp, qweight, scales, qzeros);
    gemm_kernel<<<M2_TILES * N_TILES, 256, GEMM_SMEM_BYTES>>>(bias, mul, out);
}